// round 4
// baseline (speedup 1.0000x reference)
#include <cuda_runtime.h>
#include <cuda_bf16.h>
#include <cstdint>
#include <math.h>

// Problem constants (MoELayer_76433237999752)
#define TT 4096      // tokens = B*S
#define DM 1024      // d_model
#define DH 4096      // d_hidden
#define NE 8         // experts
#define RTOT (TT*2)  // total routed rows (top-2)
#define HPAD 128     // row padding so GEMM2 A-tile reads never go OOB

// GEMM tiling
#define BM 128
#define BN 128
#define BK 32
// SMEM stage layout (bytes): Ah[128*80] Al[128*80] Bh[32*272] Bl[32*272]
#define AH_OFF 0
#define AL_OFF 10240
#define BH_OFF 20480
#define BL_OFF 29184
#define STAGE_BYTES 37888
#define NSTAGE 3
#define SMEM_BYTES (STAGE_BYTES * NSTAGE)

// ===========================================================================
// Device-global scratch
// ===========================================================================
__device__ int   g_cnt [NE];
__device__ int   g_base[NE];
__device__ int   g_tok [NE * TT];
__device__ int   g_te  [TT * 2];
__device__ int   g_ts  [TT * 2];
__device__ float g_tw  [TT * 2];
__device__ __nv_bfloat16 g_x_hi [(size_t)TT * DM];
__device__ __nv_bfloat16 g_x_lo [(size_t)TT * DM];
__device__ __nv_bfloat16 g_w1_hi[(size_t)NE * DM * DH];
__device__ __nv_bfloat16 g_w1_lo[(size_t)NE * DM * DH];
__device__ __nv_bfloat16 g_w2_hi[(size_t)NE * DH * DM];
__device__ __nv_bfloat16 g_w2_lo[(size_t)NE * DH * DM];
__device__ __nv_bfloat16 g_h_hi [(size_t)(RTOT + HPAD) * DH];
__device__ __nv_bfloat16 g_h_lo [(size_t)(RTOT + HPAD) * DH];
__device__ float         g_yp   [(size_t)RTOT * DM];

// ===========================================================================
// PTX helpers (plain sm_80-era — nothing "a"-gated)
// ===========================================================================
__device__ __forceinline__ uint32_t smem_u32(const void* p) {
    uint32_t a;
    asm("{ .reg .u64 t; cvta.to.shared.u64 t, %1; cvt.u32.u64 %0, t; }" : "=r"(a) : "l"(p));
    return a;
}
__device__ __forceinline__ void ldsm_x4(uint32_t* r, uint32_t addr) {
    asm volatile("ldmatrix.sync.aligned.m8n8.x4.shared.b16 {%0,%1,%2,%3}, [%4];"
                 : "=r"(r[0]), "=r"(r[1]), "=r"(r[2]), "=r"(r[3]) : "r"(addr));
}
__device__ __forceinline__ void ldsm_x2t(uint32_t* r, uint32_t addr) {
    asm volatile("ldmatrix.sync.aligned.m8n8.x2.trans.shared.b16 {%0,%1}, [%2];"
                 : "=r"(r[0]), "=r"(r[1]) : "r"(addr));
}
__device__ __forceinline__ void mma16816(float* c, const uint32_t* a, const uint32_t* b) {
    asm volatile("mma.sync.aligned.m16n8k16.row.col.f32.bf16.bf16.f32 "
                 "{%0,%1,%2,%3}, {%4,%5,%6,%7}, {%8,%9}, {%0,%1,%2,%3};"
                 : "+f"(c[0]), "+f"(c[1]), "+f"(c[2]), "+f"(c[3])
                 : "r"(a[0]), "r"(a[1]), "r"(a[2]), "r"(a[3]), "r"(b[0]), "r"(b[1]));
}
__device__ __forceinline__ void cp16(uint32_t dst, const void* src, uint32_t sz) {
    asm volatile("cp.async.cg.shared.global [%0], [%1], 16, %2;"
                 :: "r"(dst), "l"(src), "r"(sz) : "memory");
}
#define CP_COMMIT() asm volatile("cp.async.commit_group;" ::: "memory")
#define CP_WAIT(n)  asm volatile("cp.async.wait_group %0;" :: "n"(n) : "memory")

__device__ __forceinline__ void split4(float4 v, uint2& h, uint2& l) {
    __nv_bfloat162 h0 = __float22bfloat162_rn(make_float2(v.x, v.y));
    __nv_bfloat162 h1 = __float22bfloat162_rn(make_float2(v.z, v.w));
    float2 f0 = __bfloat1622float2(h0), f1 = __bfloat1622float2(h1);
    __nv_bfloat162 l0 = __float22bfloat162_rn(make_float2(v.x - f0.x, v.y - f0.y));
    __nv_bfloat162 l1 = __float22bfloat162_rn(make_float2(v.z - f1.x, v.w - f1.y));
    h = make_uint2(*(uint32_t*)&h0, *(uint32_t*)&h1);
    l = make_uint2(*(uint32_t*)&l0, *(uint32_t*)&l1);
}
__device__ __forceinline__ void split2(float v0, float v1, uint32_t& h, uint32_t& l) {
    __nv_bfloat162 hb = __float22bfloat162_rn(make_float2(v0, v1));
    float2 hf = __bfloat1622float2(hb);
    __nv_bfloat162 lb = __float22bfloat162_rn(make_float2(v0 - hf.x, v1 - hf.y));
    h = *(uint32_t*)&hb;
    l = *(uint32_t*)&lb;
}

// ===========================================================================
// Elementwise fp32 -> bf16 hi/lo split (grid-stride over float4)
// ===========================================================================
__global__ void split_kernel(const float* __restrict__ in,
                             __nv_bfloat16* __restrict__ oh,
                             __nv_bfloat16* __restrict__ ol, size_t n4) {
    size_t stride = (size_t)gridDim.x * blockDim.x;
    for (size_t i = (size_t)blockIdx.x * blockDim.x + threadIdx.x; i < n4; i += stride) {
        float4 v = ((const float4*)in)[i];
        uint2 h, l;
        split4(v, h, l);
        ((uint2*)oh)[i] = h;
        ((uint2*)ol)[i] = l;
    }
}

// ===========================================================================
// Routing
// ===========================================================================
__global__ void zero_cnt_kernel() {
    if (threadIdx.x < NE) g_cnt[threadIdx.x] = 0;
}

__global__ void gate_kernel(const float* __restrict__ x,
                            const float* __restrict__ Wg,
                            const float* __restrict__ bg,
                            float* __restrict__ logits_out,
                            int write_logits) {
    int t    = (blockIdx.x * blockDim.x + threadIdx.x) >> 5;
    int lane = threadIdx.x & 31;
    if (t >= TT) return;

    const float* xr = x + (size_t)t * DM;
    float acc[NE];
#pragma unroll
    for (int e = 0; e < NE; e++) acc[e] = 0.0f;
    for (int d = lane; d < DM; d += 32) {
        float xv = xr[d];
        const float* wr = Wg + (size_t)d * NE;
#pragma unroll
        for (int e = 0; e < NE; e++) acc[e] += xv * wr[e];
    }
#pragma unroll
    for (int e = 0; e < NE; e++)
#pragma unroll
        for (int o = 16; o > 0; o >>= 1)
            acc[e] += __shfl_xor_sync(0xffffffffu, acc[e], o);

    if (lane == 0) {
#pragma unroll
        for (int e = 0; e < NE; e++) acc[e] += bg[e];
        if (write_logits)
#pragma unroll
            for (int e = 0; e < NE; e++)
                logits_out[(size_t)t * NE + e] = acc[e];
        int i0 = 0; float v0 = acc[0];
#pragma unroll
        for (int e = 1; e < NE; e++) if (acc[e] > v0) { v0 = acc[e]; i0 = e; }
        int i1 = -1; float v1 = -INFINITY;
#pragma unroll
        for (int e = 0; e < NE; e++) {
            if (e == i0) continue;
            if (acc[e] > v1) { v1 = acc[e]; i1 = e; }
        }
        float ew  = expf(v1 - v0);
        float inv = 1.0f / (1.0f + ew);

        int s0 = atomicAdd(&g_cnt[i0], 1);
        g_tok[i0 * TT + s0] = t;
        int s1 = atomicAdd(&g_cnt[i1], 1);
        g_tok[i1 * TT + s1] = t;

        g_te[2*t]   = i0; g_ts[2*t]   = s0; g_tw[2*t]   = inv;
        g_te[2*t+1] = i1; g_ts[2*t+1] = s1; g_tw[2*t+1] = ew * inv;
    }
}

__global__ void prefix_kernel() {
    if (threadIdx.x == 0) {
        int s = 0;
#pragma unroll
        for (int e = 0; e < NE; e++) { g_base[e] = s; s += g_cnt[e]; }
    }
}

// ===========================================================================
// GEMM core: 128x128 tile, BK=32, 8 warps (2x4), 3-stage cp.async pipeline,
// bf16 hi/lo 3-pass mma. A gathered bf16 hi/lo, B row-major [k][n] bf16 hi/lo.
// ===========================================================================
struct TilePtrs {
    const __nv_bfloat16 *ah0, *ah1, *al0, *al1;
    uint32_t asz0, asz1;
    const __nv_bfloat16 *bh0, *bh1, *bl0, *bl1;
    int aStep, bStep;
    uint32_t aDst0, aDst1, bDst0, bDst1;
};

__device__ __forceinline__ void issue_tile(uint32_t sb, int stage, const TilePtrs& tp, int kt) {
    uint32_t s = sb + stage * STAGE_BYTES;
    int ao = kt * tp.aStep;
    int bo = kt * tp.bStep;
    cp16(s + AH_OFF + tp.aDst0, tp.ah0 + ao, tp.asz0);
    cp16(s + AH_OFF + tp.aDst1, tp.ah1 + ao, tp.asz1);
    cp16(s + AL_OFF + tp.aDst0, tp.al0 + ao, tp.asz0);
    cp16(s + AL_OFF + tp.aDst1, tp.al1 + ao, tp.asz1);
    cp16(s + BH_OFF + tp.bDst0, tp.bh0 + bo, 16);
    cp16(s + BH_OFF + tp.bDst1, tp.bh1 + bo, 16);
    cp16(s + BL_OFF + tp.bDst0, tp.bl0 + bo, 16);
    cp16(s + BL_OFF + tp.bDst1, tp.bl1 + bo, 16);
    CP_COMMIT();
}

template <int NC>
__device__ __forceinline__ void gemm_core(uint32_t sb, const TilePtrs& tp,
                                          float cacc[4][4][4],
                                          uint32_t aOff, uint32_t bOff) {
    issue_tile(sb, 0, tp, 0);
    issue_tile(sb, 1, tp, 1);
#pragma unroll 1
    for (int kt = 0; kt < NC; kt++) {
        if (kt + 1 < NC) { CP_WAIT(1); } else { CP_WAIT(0); }
        __syncthreads();
        if (kt + 2 < NC) issue_tile(sb, (kt + 2) % NSTAGE, tp, kt + 2);
        uint32_t s = sb + (kt % NSTAGE) * STAGE_BYTES;
#pragma unroll
        for (int k16 = 0; k16 < 2; k16++) {
            uint32_t ah[4][4], al[4][4], bh[4][2], bl[4][2];
#pragma unroll
            for (int mi = 0; mi < 4; mi++) {
                ldsm_x4(ah[mi], s + AH_OFF + aOff + mi * 1280 + k16 * 32);
                ldsm_x4(al[mi], s + AL_OFF + aOff + mi * 1280 + k16 * 32);
            }
#pragma unroll
            for (int ni = 0; ni < 4; ni++) {
                ldsm_x2t(bh[ni], s + BH_OFF + bOff + ni * 16 + k16 * 4352);
                ldsm_x2t(bl[ni], s + BL_OFF + bOff + ni * 16 + k16 * 4352);
            }
#pragma unroll
            for (int mi = 0; mi < 4; mi++)
#pragma unroll
                for (int ni = 0; ni < 4; ni++) {
                    mma16816(cacc[mi][ni], ah[mi], bh[ni]);
                    mma16816(cacc[mi][ni], ah[mi], bl[ni]);
                    mma16816(cacc[mi][ni], al[mi], bh[ni]);
                }
        }
    }
}

// ===========================================================================
// GEMM1: h[base+r] = relu( x[tok[r]] @ W1[e] + b1[e] )
// ===========================================================================
__global__ void __launch_bounds__(256)
moe_gemm1(const float* __restrict__ b1) {
    int e   = blockIdx.z;
    int cnt = g_cnt[e];
    int rb  = blockIdx.y * BM;
    if (rb >= cnt) return;
    int nb   = blockIdx.x * BN;
    int base = g_base[e];

    extern __shared__ __align__(128) char smem[];
    uint32_t sb = smem_u32(smem);

    int tid  = threadIdx.x;
    int lane = tid & 31, wid = tid >> 5;
    int wm = wid >> 2, wn = wid & 3;

    TilePtrs tp;
    {
        int r0 = tid >> 2, sg0 = tid & 3;
        int c1 = tid + 256;
        int r1 = c1 >> 2, sg1 = c1 & 3;
        bool v0 = (rb + r0) < cnt, v1 = (rb + r1) < cnt;
        int t0 = g_tok[e * TT + (v0 ? rb + r0 : 0)];
        int t1 = g_tok[e * TT + (v1 ? rb + r1 : 0)];
        tp.ah0 = g_x_hi + (size_t)t0 * DM + sg0 * 8;
        tp.al0 = g_x_lo + (size_t)t0 * DM + sg0 * 8;
        tp.ah1 = g_x_hi + (size_t)t1 * DM + sg1 * 8;
        tp.al1 = g_x_lo + (size_t)t1 * DM + sg1 * 8;
        tp.asz0 = v0 ? 16 : 0;
        tp.asz1 = v1 ? 16 : 0;
        tp.aDst0 = (uint32_t)r0 * 80 + sg0 * 16;
        tp.aDst1 = (uint32_t)r1 * 80 + sg1 * 16;
        tp.aStep = BK;
        int kr0 = tid >> 4, bs0 = tid & 15;
        int kc1 = tid + 256;
        int kr1 = kc1 >> 4, bs1 = kc1 & 15;
        size_t wbase = (size_t)e * DM * DH;
        tp.bh0 = g_w1_hi + wbase + (size_t)kr0 * DH + nb + bs0 * 8;
        tp.bl0 = g_w1_lo + wbase + (size_t)kr0 * DH + nb + bs0 * 8;
        tp.bh1 = g_w1_hi + wbase + (size_t)kr1 * DH + nb + bs1 * 8;
        tp.bl1 = g_w1_lo + wbase + (size_t)kr1 * DH + nb + bs1 * 8;
        tp.bDst0 = (uint32_t)kr0 * 272 + bs0 * 16;
        tp.bDst1 = (uint32_t)kr1 * 272 + bs1 * 16;
        tp.bStep = BK * DH;
    }

    uint32_t aOff = (uint32_t)(wm * 64 + (lane & 7) + ((lane >> 3) & 1) * 8) * 80
                  + (lane >> 4) * 16;
    uint32_t bOff = (uint32_t)(lane & 15) * 272 + wn * 64;

    float cacc[4][4][4];
#pragma unroll
    for (int mi = 0; mi < 4; mi++)
#pragma unroll
        for (int ni = 0; ni < 4; ni++)
#pragma unroll
            for (int q = 0; q < 4; q++) cacc[mi][ni][q] = 0.0f;

    gemm_core<DM / BK>(sb, tp, cacc, aOff, bOff);

    const float* bb = b1 + (size_t)e * DH + nb;
    int er = wm * 64 + (lane >> 2);
    int ec = wn * 32 + (lane & 3) * 2;
#pragma unroll
    for (int mi = 0; mi < 4; mi++) {
#pragma unroll
        for (int rr = 0; rr < 2; rr++) {
            int m = er + mi * 16 + rr * 8;
            if (rb + m >= cnt) continue;
            size_t rowoff = (size_t)(base + rb + m) * DH + nb;
#pragma unroll
            for (int ni = 0; ni < 4; ni++) {
                int c = ec + ni * 8;
                float v0 = cacc[mi][ni][rr * 2 + 0] + bb[c];
                float v1 = cacc[mi][ni][rr * 2 + 1] + bb[c + 1];
                v0 = v0 > 0.f ? v0 : 0.f;
                v1 = v1 > 0.f ? v1 : 0.f;
                uint32_t h, l;
                split2(v0, v1, h, l);
                *(uint32_t*)(g_h_hi + rowoff + c) = h;
                *(uint32_t*)(g_h_lo + rowoff + c) = l;
            }
        }
    }
}

// ===========================================================================
// GEMM2: yp[base+r] = h[base+r] @ W2[e] + b2[e]
// ===========================================================================
__global__ void __launch_bounds__(256)
moe_gemm2(const float* __restrict__ b2) {
    int e   = blockIdx.z;
    int cnt = g_cnt[e];
    int rb  = blockIdx.y * BM;
    if (rb >= cnt) return;
    int nb   = blockIdx.x * BN;
    int base = g_base[e];

    extern __shared__ __align__(128) char smem[];
    uint32_t sb = smem_u32(smem);

    int tid  = threadIdx.x;
    int lane = tid & 31, wid = tid >> 5;
    int wm = wid >> 2, wn = wid & 3;

    TilePtrs tp;
    {
        int r0 = tid >> 2, sg0 = tid & 3;
        int c1 = tid + 256;
        int r1 = c1 >> 2, sg1 = c1 & 3;
        size_t a0 = (size_t)(base + rb + r0) * DH + sg0 * 8;
        size_t a1 = (size_t)(base + rb + r1) * DH + sg1 * 8;
        tp.ah0 = g_h_hi + a0; tp.al0 = g_h_lo + a0;
        tp.ah1 = g_h_hi + a1; tp.al1 = g_h_lo + a1;
        tp.asz0 = 16; tp.asz1 = 16;
        tp.aDst0 = (uint32_t)r0 * 80 + sg0 * 16;
        tp.aDst1 = (uint32_t)r1 * 80 + sg1 * 16;
        tp.aStep = BK;
        int kr0 = tid >> 4, bs0 = tid & 15;
        int kc1 = tid + 256;
        int kr1 = kc1 >> 4, bs1 = kc1 & 15;
        size_t wbase = (size_t)e * DH * DM;
        tp.bh0 = g_w2_hi + wbase + (size_t)kr0 * DM + nb + bs0 * 8;
        tp.bl0 = g_w2_lo + wbase + (size_t)kr0 * DM + nb + bs0 * 8;
        tp.bh1 = g_w2_hi + wbase + (size_t)kr1 * DM + nb + bs1 * 8;
        tp.bl1 = g_w2_lo + wbase + (size_t)kr1 * DM + nb + bs1 * 8;
        tp.bDst0 = (uint32_t)kr0 * 272 + bs0 * 16;
        tp.bDst1 = (uint32_t)kr1 * 272 + bs1 * 16;
        tp.bStep = BK * DM;
    }

    uint32_t aOff = (uint32_t)(wm * 64 + (lane & 7) + ((lane >> 3) & 1) * 8) * 80
                  + (lane >> 4) * 16;
    uint32_t bOff = (uint32_t)(lane & 15) * 272 + wn * 64;

    float cacc[4][4][4];
#pragma unroll
    for (int mi = 0; mi < 4; mi++)
#pragma unroll
        for (int ni = 0; ni < 4; ni++)
#pragma unroll
            for (int q = 0; q < 4; q++) cacc[mi][ni][q] = 0.0f;

    gemm_core<DH / BK>(sb, tp, cacc, aOff, bOff);

    const float* bb = b2 + (size_t)e * DM + nb;
    int er = wm * 64 + (lane >> 2);
    int ec = wn * 32 + (lane & 3) * 2;
#pragma unroll
    for (int mi = 0; mi < 4; mi++) {
#pragma unroll
        for (int rr = 0; rr < 2; rr++) {
            int m = er + mi * 16 + rr * 8;
            if (rb + m >= cnt) continue;
            float* yrow = g_yp + (size_t)(base + rb + m) * DM + nb;
#pragma unroll
            for (int ni = 0; ni < 4; ni++) {
                int c = ec + ni * 8;
                float2 o;
                o.x = cacc[mi][ni][rr * 2 + 0] + bb[c];
                o.y = cacc[mi][ni][rr * 2 + 1] + bb[c + 1];
                *(float2*)(yrow + c) = o;
            }
        }
    }
}

// ===========================================================================
// combine: out[t] = w0*yp[r0] + w1*yp[r1]
// ===========================================================================
__global__ void combine_kernel(float* __restrict__ out) {
    int t = blockIdx.x;
    int c = threadIdx.x;
    int e0 = g_te[2*t],   e1 = g_te[2*t+1];
    int r0 = g_base[e0] + g_ts[2*t];
    int r1 = g_base[e1] + g_ts[2*t+1];
    float w0 = g_tw[2*t], w1 = g_tw[2*t+1];
    float4 a = ((const float4*)(g_yp + (size_t)r0 * DM))[c];
    float4 b = ((const float4*)(g_yp + (size_t)r1 * DM))[c];
    float4 o;
    o.x = w0 * a.x + w1 * b.x;
    o.y = w0 * a.y + w1 * b.y;
    o.z = w0 * a.z + w1 * b.z;
    o.w = w0 * a.w + w1 * b.w;
    ((float4*)(out + (size_t)t * DM))[c] = o;
}

// ===========================================================================
// Launch
// ===========================================================================
extern "C" void kernel_launch(void* const* d_in, const int* in_sizes, int n_in,
                              void* d_out, int out_size) {
    const float* x  = (const float*)d_in[0];
    const float* Wg = (const float*)d_in[1];
    const float* bg = (const float*)d_in[2];
    const float* W1 = (const float*)d_in[3];
    const float* b1 = (const float*)d_in[4];
    const float* W2 = (const float*)d_in[5];
    const float* b2 = (const float*)d_in[6];

    float* out_y = (float*)d_out;
    int write_logits = (out_size >= TT * (DM + NE)) ? 1 : 0;
    float* logits = out_y + (size_t)TT * DM;

    cudaFuncSetAttribute(moe_gemm1, cudaFuncAttributeMaxDynamicSharedMemorySize, SMEM_BYTES);
    cudaFuncSetAttribute(moe_gemm2, cudaFuncAttributeMaxDynamicSharedMemorySize, SMEM_BYTES);

    __nv_bfloat16 *xh, *xl, *w1h, *w1l, *w2h, *w2l;
    cudaGetSymbolAddress((void**)&xh,  g_x_hi);
    cudaGetSymbolAddress((void**)&xl,  g_x_lo);
    cudaGetSymbolAddress((void**)&w1h, g_w1_hi);
    cudaGetSymbolAddress((void**)&w1l, g_w1_lo);
    cudaGetSymbolAddress((void**)&w2h, g_w2_hi);
    cudaGetSymbolAddress((void**)&w2l, g_w2_lo);

    zero_cnt_kernel<<<1, 32>>>();
    split_kernel<<<2048, 256>>>(x,  xh,  xl,  (size_t)TT * DM / 4);
    split_kernel<<<8192, 256>>>(W1, w1h, w1l, (size_t)NE * DM * DH / 4);
    split_kernel<<<8192, 256>>>(W2, w2h, w2l, (size_t)NE * DH * DM / 4);
    gate_kernel<<<(TT * 32) / 256, 256>>>(x, Wg, bg, logits, write_logits);
    prefix_kernel<<<1, 32>>>();

    moe_gemm1<<<dim3(DH / BN, TT / BM, NE), 256, SMEM_BYTES>>>(b1);
    moe_gemm2<<<dim3(DM / BN, TT / BM, NE), 256, SMEM_BYTES>>>(b2);

    combine_kernel<<<TT, DM / 4>>>(out_y);
}

// round 5
// speedup vs baseline: 1.0035x; 1.0035x over previous
#include <cuda_runtime.h>
#include <cuda_bf16.h>
#include <cstdint>
#include <math.h>

// Problem constants (MoELayer_76433237999752)
#define TT 4096      // tokens = B*S
#define DM 1024      // d_model
#define DH 4096      // d_hidden
#define NE 8         // experts
#define RTOT (TT*2)  // total routed rows (top-2)
#define HPAD 128     // row padding so GEMM2 A-tile reads never go OOB

// GEMM tiling: CTA tile 128x128, BK=32, 512 threads = 16 warps (2 x 8),
// warp tile 64x16.
#define BM 128
#define BN 128
#define BK 32
#define NTHREADS 512
// SMEM stage layout (bytes): Ah[128*80] Al[128*80] Bh[32*272] Bl[32*272]
#define AH_OFF 0
#define AL_OFF 10240
#define BH_OFF 20480
#define BL_OFF 29184
#define STAGE_BYTES 37888
#define NSTAGE 3
#define SMEM_BYTES (STAGE_BYTES * NSTAGE)

// ===========================================================================
// Device-global scratch
// ===========================================================================
__device__ int   g_cnt [NE];
__device__ int   g_base[NE];
__device__ int   g_tok [NE * TT];
__device__ int   g_te  [TT * 2];
__device__ int   g_ts  [TT * 2];
__device__ float g_tw  [TT * 2];
__device__ __nv_bfloat16 g_x_hi [(size_t)TT * DM];
__device__ __nv_bfloat16 g_x_lo [(size_t)TT * DM];
__device__ __nv_bfloat16 g_w1_hi[(size_t)NE * DM * DH];
__device__ __nv_bfloat16 g_w1_lo[(size_t)NE * DM * DH];
__device__ __nv_bfloat16 g_w2_hi[(size_t)NE * DH * DM];
__device__ __nv_bfloat16 g_w2_lo[(size_t)NE * DH * DM];
__device__ __nv_bfloat16 g_h_hi [(size_t)(RTOT + HPAD) * DH];
__device__ __nv_bfloat16 g_h_lo [(size_t)(RTOT + HPAD) * DH];
__device__ float         g_yp   [(size_t)RTOT * DM];

// ===========================================================================
// PTX helpers (plain sm_80-era — nothing "a"-gated)
// ===========================================================================
__device__ __forceinline__ uint32_t smem_u32(const void* p) {
    uint32_t a;
    asm("{ .reg .u64 t; cvta.to.shared.u64 t, %1; cvt.u32.u64 %0, t; }" : "=r"(a) : "l"(p));
    return a;
}
__device__ __forceinline__ void ldsm_x4(uint32_t* r, uint32_t addr) {
    asm volatile("ldmatrix.sync.aligned.m8n8.x4.shared.b16 {%0,%1,%2,%3}, [%4];"
                 : "=r"(r[0]), "=r"(r[1]), "=r"(r[2]), "=r"(r[3]) : "r"(addr));
}
__device__ __forceinline__ void ldsm_x2t(uint32_t* r, uint32_t addr) {
    asm volatile("ldmatrix.sync.aligned.m8n8.x2.trans.shared.b16 {%0,%1}, [%2];"
                 : "=r"(r[0]), "=r"(r[1]) : "r"(addr));
}
__device__ __forceinline__ void mma16816(float* c, const uint32_t* a, const uint32_t* b) {
    asm volatile("mma.sync.aligned.m16n8k16.row.col.f32.bf16.bf16.f32 "
                 "{%0,%1,%2,%3}, {%4,%5,%6,%7}, {%8,%9}, {%0,%1,%2,%3};"
                 : "+f"(c[0]), "+f"(c[1]), "+f"(c[2]), "+f"(c[3])
                 : "r"(a[0]), "r"(a[1]), "r"(a[2]), "r"(a[3]), "r"(b[0]), "r"(b[1]));
}
__device__ __forceinline__ void cp16(uint32_t dst, const void* src, uint32_t sz) {
    asm volatile("cp.async.cg.shared.global [%0], [%1], 16, %2;"
                 :: "r"(dst), "l"(src), "r"(sz) : "memory");
}
#define CP_COMMIT() asm volatile("cp.async.commit_group;" ::: "memory")
#define CP_WAIT(n)  asm volatile("cp.async.wait_group %0;" :: "n"(n) : "memory")

__device__ __forceinline__ void split4(float4 v, uint2& h, uint2& l) {
    __nv_bfloat162 h0 = __float22bfloat162_rn(make_float2(v.x, v.y));
    __nv_bfloat162 h1 = __float22bfloat162_rn(make_float2(v.z, v.w));
    float2 f0 = __bfloat1622float2(h0), f1 = __bfloat1622float2(h1);
    __nv_bfloat162 l0 = __float22bfloat162_rn(make_float2(v.x - f0.x, v.y - f0.y));
    __nv_bfloat162 l1 = __float22bfloat162_rn(make_float2(v.z - f1.x, v.w - f1.y));
    h = make_uint2(*(uint32_t*)&h0, *(uint32_t*)&h1);
    l = make_uint2(*(uint32_t*)&l0, *(uint32_t*)&l1);
}
__device__ __forceinline__ void split2(float v0, float v1, uint32_t& h, uint32_t& l) {
    __nv_bfloat162 hb = __float22bfloat162_rn(make_float2(v0, v1));
    float2 hf = __bfloat1622float2(hb);
    __nv_bfloat162 lb = __float22bfloat162_rn(make_float2(v0 - hf.x, v1 - hf.y));
    h = *(uint32_t*)&hb;
    l = *(uint32_t*)&lb;
}

// ===========================================================================
// Elementwise fp32 -> bf16 hi/lo split (weights)
// ===========================================================================
__global__ void split_kernel(const float* __restrict__ in,
                             __nv_bfloat16* __restrict__ oh,
                             __nv_bfloat16* __restrict__ ol, size_t n4) {
    size_t stride = (size_t)gridDim.x * blockDim.x;
    for (size_t i = (size_t)blockIdx.x * blockDim.x + threadIdx.x; i < n4; i += stride) {
        float4 v = ((const float4*)in)[i];
        uint2 h, l;
        split4(v, h, l);
        ((uint2*)oh)[i] = h;
        ((uint2*)ol)[i] = l;
    }
}

// ===========================================================================
// Routing (gate also writes the x hi/lo split)
// ===========================================================================
__global__ void zero_cnt_kernel() {
    if (threadIdx.x < NE) g_cnt[threadIdx.x] = 0;
}

__global__ void gate_kernel(const float* __restrict__ x,
                            const float* __restrict__ Wg,
                            const float* __restrict__ bg,
                            float* __restrict__ logits_out,
                            int write_logits) {
    int t    = (blockIdx.x * blockDim.x + threadIdx.x) >> 5;
    int lane = threadIdx.x & 31;
    if (t >= TT) return;

    const float* xr = x + (size_t)t * DM;
    float acc[NE];
#pragma unroll
    for (int e = 0; e < NE; e++) acc[e] = 0.0f;
    for (int d = lane; d < DM; d += 32) {
        float xv = xr[d];
        // fused x hi/lo split
        __nv_bfloat16 hh = __float2bfloat16_rn(xv);
        g_x_hi[(size_t)t * DM + d] = hh;
        g_x_lo[(size_t)t * DM + d] = __float2bfloat16_rn(xv - __bfloat162float(hh));
        const float* wr = Wg + (size_t)d * NE;
#pragma unroll
        for (int e = 0; e < NE; e++) acc[e] += xv * wr[e];
    }
#pragma unroll
    for (int e = 0; e < NE; e++)
#pragma unroll
        for (int o = 16; o > 0; o >>= 1)
            acc[e] += __shfl_xor_sync(0xffffffffu, acc[e], o);

    if (lane == 0) {
#pragma unroll
        for (int e = 0; e < NE; e++) acc[e] += bg[e];
        if (write_logits)
#pragma unroll
            for (int e = 0; e < NE; e++)
                logits_out[(size_t)t * NE + e] = acc[e];
        int i0 = 0; float v0 = acc[0];
#pragma unroll
        for (int e = 1; e < NE; e++) if (acc[e] > v0) { v0 = acc[e]; i0 = e; }
        int i1 = -1; float v1 = -INFINITY;
#pragma unroll
        for (int e = 0; e < NE; e++) {
            if (e == i0) continue;
            if (acc[e] > v1) { v1 = acc[e]; i1 = e; }
        }
        float ew  = expf(v1 - v0);
        float inv = 1.0f / (1.0f + ew);

        int s0 = atomicAdd(&g_cnt[i0], 1);
        g_tok[i0 * TT + s0] = t;
        int s1 = atomicAdd(&g_cnt[i1], 1);
        g_tok[i1 * TT + s1] = t;

        g_te[2*t]   = i0; g_ts[2*t]   = s0; g_tw[2*t]   = inv;
        g_te[2*t+1] = i1; g_ts[2*t+1] = s1; g_tw[2*t+1] = ew * inv;
    }
}

__global__ void prefix_kernel() {
    if (threadIdx.x == 0) {
        int s = 0;
#pragma unroll
        for (int e = 0; e < NE; e++) { g_base[e] = s; s += g_cnt[e]; }
    }
}

// ===========================================================================
// GEMM core: 128x128 CTA tile, BK=32, 16 warps (2x8), warp tile 64x16,
// 3-stage cp.async pipeline, bf16 hi/lo 3-pass mma (pass-major ordering).
// ===========================================================================
struct TilePtrs {
    const __nv_bfloat16 *ah, *al;   // one A 16B chunk per thread
    uint32_t asz;                    // 16 or 0 (zero-fill)
    const __nv_bfloat16 *bh, *bl;   // one B 16B chunk per thread
    int aStep, bStep;                // elems to advance per kt
    uint32_t aDst, bDst;             // smem offsets within stage
};

__device__ __forceinline__ void issue_tile(uint32_t sb, int stage, const TilePtrs& tp, int kt) {
    uint32_t s = sb + stage * STAGE_BYTES;
    int ao = kt * tp.aStep;
    int bo = kt * tp.bStep;
    cp16(s + AH_OFF + tp.aDst, tp.ah + ao, tp.asz);
    cp16(s + AL_OFF + tp.aDst, tp.al + ao, tp.asz);
    cp16(s + BH_OFF + tp.bDst, tp.bh + bo, 16);
    cp16(s + BL_OFF + tp.bDst, tp.bl + bo, 16);
    CP_COMMIT();
}

template <int NC>
__device__ __forceinline__ void gemm_core(uint32_t sb, const TilePtrs& tp,
                                          float cacc[4][2][4],
                                          uint32_t aOff, uint32_t bOff) {
    issue_tile(sb, 0, tp, 0);
    issue_tile(sb, 1, tp, 1);
#pragma unroll 1
    for (int kt = 0; kt < NC; kt++) {
        if (kt + 1 < NC) { CP_WAIT(1); } else { CP_WAIT(0); }
        __syncthreads();
        if (kt + 2 < NC) issue_tile(sb, (kt + 2) % NSTAGE, tp, kt + 2);
        uint32_t s = sb + (kt % NSTAGE) * STAGE_BYTES;
#pragma unroll
        for (int k16 = 0; k16 < 2; k16++) {
            uint32_t ah[4][4], al[4][4], bh[2][2], bl[2][2];
#pragma unroll
            for (int mi = 0; mi < 4; mi++) {
                ldsm_x4(ah[mi], s + AH_OFF + aOff + mi * 1280 + k16 * 32);
                ldsm_x4(al[mi], s + AL_OFF + aOff + mi * 1280 + k16 * 32);
            }
#pragma unroll
            for (int ni = 0; ni < 2; ni++) {
                ldsm_x2t(bh[ni], s + BH_OFF + bOff + ni * 16 + k16 * 4352);
                ldsm_x2t(bl[ni], s + BL_OFF + bOff + ni * 16 + k16 * 4352);
            }
            // pass-major: same-accumulator MMAs are 8 instructions apart
#pragma unroll
            for (int mi = 0; mi < 4; mi++)
#pragma unroll
                for (int ni = 0; ni < 2; ni++)
                    mma16816(cacc[mi][ni], ah[mi], bh[ni]);
#pragma unroll
            for (int mi = 0; mi < 4; mi++)
#pragma unroll
                for (int ni = 0; ni < 2; ni++)
                    mma16816(cacc[mi][ni], ah[mi], bl[ni]);
#pragma unroll
            for (int mi = 0; mi < 4; mi++)
#pragma unroll
                for (int ni = 0; ni < 2; ni++)
                    mma16816(cacc[mi][ni], al[mi], bh[ni]);
        }
    }
}

// warp layout helpers: 16 warps as (wm, wn) = (wid>>3, wid&7)
// A ldmatrix offset: rows wm*64 + mi*16 + [0..15], k-half by lane>>4
// B ldmatrix offset: k rows lane&15, cols wn*16 + ni*8
__device__ __forceinline__ uint32_t calc_aoff(int wm, int lane) {
    return (uint32_t)(wm * 64 + (lane & 7) + ((lane >> 3) & 1) * 8) * 80
         + (lane >> 4) * 16;
}
__device__ __forceinline__ uint32_t calc_boff(int wn, int lane) {
    return (uint32_t)(lane & 15) * 272 + wn * 32;
}

// ===========================================================================
// GEMM1: h[base+r] = relu( x[tok[r]] @ W1[e] + b1[e] )
// ===========================================================================
__global__ void __launch_bounds__(NTHREADS)
moe_gemm1(const float* __restrict__ b1) {
    int e   = blockIdx.z;
    int cnt = g_cnt[e];
    int rb  = blockIdx.y * BM;
    if (rb >= cnt) return;
    int nb   = blockIdx.x * BN;
    int base = g_base[e];

    extern __shared__ __align__(128) char smem[];
    uint32_t sb = smem_u32(smem);

    int tid  = threadIdx.x;
    int lane = tid & 31, wid = tid >> 5;
    int wm = wid >> 3, wn = wid & 7;

    TilePtrs tp;
    {
        int r = tid >> 2, sg = tid & 3;          // A: 512 chunks, 4/row
        bool v = (rb + r) < cnt;
        int tok = g_tok[e * TT + (v ? rb + r : 0)];
        tp.ah  = g_x_hi + (size_t)tok * DM + sg * 8;
        tp.al  = g_x_lo + (size_t)tok * DM + sg * 8;
        tp.asz = v ? 16 : 0;
        tp.aDst = (uint32_t)r * 80 + sg * 16;
        tp.aStep = BK;
        int kr = tid >> 4, bs = tid & 15;        // B: 512 chunks, 16/krow
        size_t wbase = (size_t)e * DM * DH;
        tp.bh = g_w1_hi + wbase + (size_t)kr * DH + nb + bs * 8;
        tp.bl = g_w1_lo + wbase + (size_t)kr * DH + nb + bs * 8;
        tp.bDst = (uint32_t)kr * 272 + bs * 16;
        tp.bStep = BK * DH;
    }

    uint32_t aOff = calc_aoff(wm, lane);
    uint32_t bOff = calc_boff(wn, lane);

    float cacc[4][2][4];
#pragma unroll
    for (int mi = 0; mi < 4; mi++)
#pragma unroll
        for (int ni = 0; ni < 2; ni++)
#pragma unroll
            for (int q = 0; q < 4; q++) cacc[mi][ni][q] = 0.0f;

    gemm_core<DM / BK>(sb, tp, cacc, aOff, bOff);

    const float* bb = b1 + (size_t)e * DH + nb;
    int er = wm * 64 + (lane >> 2);
    int ec = wn * 16 + (lane & 3) * 2;
#pragma unroll
    for (int mi = 0; mi < 4; mi++) {
#pragma unroll
        for (int rr = 0; rr < 2; rr++) {
            int m = er + mi * 16 + rr * 8;
            if (rb + m >= cnt) continue;
            size_t rowoff = (size_t)(base + rb + m) * DH + nb;
#pragma unroll
            for (int ni = 0; ni < 2; ni++) {
                int c = ec + ni * 8;
                float v0 = cacc[mi][ni][rr * 2 + 0] + bb[c];
                float v1 = cacc[mi][ni][rr * 2 + 1] + bb[c + 1];
                v0 = v0 > 0.f ? v0 : 0.f;
                v1 = v1 > 0.f ? v1 : 0.f;
                uint32_t h, l;
                split2(v0, v1, h, l);
                *(uint32_t*)(g_h_hi + rowoff + c) = h;
                *(uint32_t*)(g_h_lo + rowoff + c) = l;
            }
        }
    }
}

// ===========================================================================
// GEMM2: yp[base+r] = h[base+r] @ W2[e] + b2[e]
// ===========================================================================
__global__ void __launch_bounds__(NTHREADS)
moe_gemm2(const float* __restrict__ b2) {
    int e   = blockIdx.z;
    int cnt = g_cnt[e];
    int rb  = blockIdx.y * BM;
    if (rb >= cnt) return;
    int nb   = blockIdx.x * BN;
    int base = g_base[e];

    extern __shared__ __align__(128) char smem[];
    uint32_t sb = smem_u32(smem);

    int tid  = threadIdx.x;
    int lane = tid & 31, wid = tid >> 5;
    int wm = wid >> 3, wn = wid & 7;

    TilePtrs tp;
    {
        int r = tid >> 2, sg = tid & 3;
        size_t a0 = (size_t)(base + rb + r) * DH + sg * 8;   // HPAD covers tails
        tp.ah  = g_h_hi + a0;
        tp.al  = g_h_lo + a0;
        tp.asz = 16;
        tp.aDst = (uint32_t)r * 80 + sg * 16;
        tp.aStep = BK;
        int kr = tid >> 4, bs = tid & 15;
        size_t wbase = (size_t)e * DH * DM;
        tp.bh = g_w2_hi + wbase + (size_t)kr * DM + nb + bs * 8;
        tp.bl = g_w2_lo + wbase + (size_t)kr * DM + nb + bs * 8;
        tp.bDst = (uint32_t)kr * 272 + bs * 16;
        tp.bStep = BK * DM;
    }

    uint32_t aOff = calc_aoff(wm, lane);
    uint32_t bOff = calc_boff(wn, lane);

    float cacc[4][2][4];
#pragma unroll
    for (int mi = 0; mi < 4; mi++)
#pragma unroll
        for (int ni = 0; ni < 2; ni++)
#pragma unroll
            for (int q = 0; q < 4; q++) cacc[mi][ni][q] = 0.0f;

    gemm_core<DH / BK>(sb, tp, cacc, aOff, bOff);

    const float* bb = b2 + (size_t)e * DM + nb;
    int er = wm * 64 + (lane >> 2);
    int ec = wn * 16 + (lane & 3) * 2;
#pragma unroll
    for (int mi = 0; mi < 4; mi++) {
#pragma unroll
        for (int rr = 0; rr < 2; rr++) {
            int m = er + mi * 16 + rr * 8;
            if (rb + m >= cnt) continue;
            float* yrow = g_yp + (size_t)(base + rb + m) * DM + nb;
#pragma unroll
            for (int ni = 0; ni < 2; ni++) {
                int c = ec + ni * 8;
                float2 o;
                o.x = cacc[mi][ni][rr * 2 + 0] + bb[c];
                o.y = cacc[mi][ni][rr * 2 + 1] + bb[c + 1];
                *(float2*)(yrow + c) = o;
            }
        }
    }
}

// ===========================================================================
// combine: out[t] = w0*yp[r0] + w1*yp[r1]
// ===========================================================================
__global__ void combine_kernel(float* __restrict__ out) {
    int t = blockIdx.x;
    int c = threadIdx.x;
    int e0 = g_te[2*t],   e1 = g_te[2*t+1];
    int r0 = g_base[e0] + g_ts[2*t];
    int r1 = g_base[e1] + g_ts[2*t+1];
    float w0 = g_tw[2*t], w1 = g_tw[2*t+1];
    float4 a = ((const float4*)(g_yp + (size_t)r0 * DM))[c];
    float4 b = ((const float4*)(g_yp + (size_t)r1 * DM))[c];
    float4 o;
    o.x = w0 * a.x + w1 * b.x;
    o.y = w0 * a.y + w1 * b.y;
    o.z = w0 * a.z + w1 * b.z;
    o.w = w0 * a.w + w1 * b.w;
    ((float4*)(out + (size_t)t * DM))[c] = o;
}

// ===========================================================================
// Launch
// ===========================================================================
extern "C" void kernel_launch(void* const* d_in, const int* in_sizes, int n_in,
                              void* d_out, int out_size) {
    const float* x  = (const float*)d_in[0];
    const float* Wg = (const float*)d_in[1];
    const float* bg = (const float*)d_in[2];
    const float* W1 = (const float*)d_in[3];
    const float* b1 = (const float*)d_in[4];
    const float* W2 = (const float*)d_in[5];
    const float* b2 = (const float*)d_in[6];

    float* out_y = (float*)d_out;
    int write_logits = (out_size >= TT * (DM + NE)) ? 1 : 0;
    float* logits = out_y + (size_t)TT * DM;

    cudaFuncSetAttribute(moe_gemm1, cudaFuncAttributeMaxDynamicSharedMemorySize, SMEM_BYTES);
    cudaFuncSetAttribute(moe_gemm2, cudaFuncAttributeMaxDynamicSharedMemorySize, SMEM_BYTES);

    __nv_bfloat16 *w1h, *w1l, *w2h, *w2l;
    cudaGetSymbolAddress((void**)&w1h, g_w1_hi);
    cudaGetSymbolAddress((void**)&w1l, g_w1_lo);
    cudaGetSymbolAddress((void**)&w2h, g_w2_hi);
    cudaGetSymbolAddress((void**)&w2l, g_w2_lo);

    zero_cnt_kernel<<<1, 32>>>();
    split_kernel<<<8192, 256>>>(W1, w1h, w1l, (size_t)NE * DM * DH / 4);
    split_kernel<<<8192, 256>>>(W2, w2h, w2l, (size_t)NE * DH * DM / 4);
    gate_kernel<<<(TT * 32) / 256, 256>>>(x, Wg, bg, logits, write_logits);
    prefix_kernel<<<1, 32>>>();

    moe_gemm1<<<dim3(DH / BN, TT / BM, NE), NTHREADS, SMEM_BYTES>>>(b1);
    moe_gemm2<<<dim3(DM / BN, TT / BM, NE), NTHREADS, SMEM_BYTES>>>(b2);

    combine_kernel<<<TT, DM / 4>>>(out_y);
}

// round 6
// speedup vs baseline: 1.1200x; 1.1161x over previous
#include <cuda_runtime.h>
#include <cuda_bf16.h>
#include <cstdint>
#include <math.h>

// Problem constants (MoELayer_76433237999752)
#define TT 4096      // tokens = B*S
#define DM 1024      // d_model
#define DH 4096      // d_hidden
#define NE 8         // experts
#define RTOT (TT*2)  // total routed rows (top-2)
#define HPAD 128     // row padding so GEMM2 A-tile reads never go OOB

// GEMM tiling: CTA tile 128x128, BK=32, 256 threads = 8 warps (2 x 4),
// warp tile 64x32, 2-stage cp.async, target 2 CTAs/SM.
#define BM 128
#define BN 128
#define BK 32
#define NTHREADS 256
// SMEM stage layout (bytes): Ah[128*80] Al[128*80] Bh[32*272] Bl[32*272]
#define AH_OFF 0
#define AL_OFF 10240
#define BH_OFF 20480
#define BL_OFF 29184
#define STAGE_BYTES 37888
#define NSTAGE 2
#define SMEM_BYTES (STAGE_BYTES * NSTAGE)   // 75776

// ===========================================================================
// Device-global scratch
// ===========================================================================
__device__ int   g_cnt [NE];
__device__ int   g_base[NE];
__device__ int   g_tok [NE * TT];
__device__ int   g_te  [TT * 2];
__device__ int   g_ts  [TT * 2];
__device__ float g_tw  [TT * 2];
__device__ __nv_bfloat16 g_x_hi [(size_t)TT * DM];
__device__ __nv_bfloat16 g_x_lo [(size_t)TT * DM];
__device__ __nv_bfloat16 g_w1_hi[(size_t)NE * DM * DH];
__device__ __nv_bfloat16 g_w1_lo[(size_t)NE * DM * DH];
__device__ __nv_bfloat16 g_w2_hi[(size_t)NE * DH * DM];
__device__ __nv_bfloat16 g_w2_lo[(size_t)NE * DH * DM];
__device__ __nv_bfloat16 g_h_hi [(size_t)(RTOT + HPAD) * DH];
__device__ __nv_bfloat16 g_h_lo [(size_t)(RTOT + HPAD) * DH];
__device__ float         g_yp   [(size_t)RTOT * DM];

// ===========================================================================
// PTX helpers (plain sm_80-era — nothing "a"-gated)
// ===========================================================================
__device__ __forceinline__ uint32_t smem_u32(const void* p) {
    uint32_t a;
    asm("{ .reg .u64 t; cvta.to.shared.u64 t, %1; cvt.u32.u64 %0, t; }" : "=r"(a) : "l"(p));
    return a;
}
__device__ __forceinline__ void ldsm_x4(uint32_t* r, uint32_t addr) {
    asm volatile("ldmatrix.sync.aligned.m8n8.x4.shared.b16 {%0,%1,%2,%3}, [%4];"
                 : "=r"(r[0]), "=r"(r[1]), "=r"(r[2]), "=r"(r[3]) : "r"(addr));
}
__device__ __forceinline__ void ldsm_x2t(uint32_t* r, uint32_t addr) {
    asm volatile("ldmatrix.sync.aligned.m8n8.x2.trans.shared.b16 {%0,%1}, [%2];"
                 : "=r"(r[0]), "=r"(r[1]) : "r"(addr));
}
__device__ __forceinline__ void mma16816(float* c, const uint32_t* a, const uint32_t* b) {
    asm volatile("mma.sync.aligned.m16n8k16.row.col.f32.bf16.bf16.f32 "
                 "{%0,%1,%2,%3}, {%4,%5,%6,%7}, {%8,%9}, {%0,%1,%2,%3};"
                 : "+f"(c[0]), "+f"(c[1]), "+f"(c[2]), "+f"(c[3])
                 : "r"(a[0]), "r"(a[1]), "r"(a[2]), "r"(a[3]), "r"(b[0]), "r"(b[1]));
}
__device__ __forceinline__ void cp16(uint32_t dst, const void* src, uint32_t sz) {
    asm volatile("cp.async.cg.shared.global [%0], [%1], 16, %2;"
                 :: "r"(dst), "l"(src), "r"(sz) : "memory");
}
#define CP_COMMIT() asm volatile("cp.async.commit_group;" ::: "memory")
#define CP_WAIT(n)  asm volatile("cp.async.wait_group %0;" :: "n"(n) : "memory")

__device__ __forceinline__ void split4(float4 v, uint2& h, uint2& l) {
    __nv_bfloat162 h0 = __float22bfloat162_rn(make_float2(v.x, v.y));
    __nv_bfloat162 h1 = __float22bfloat162_rn(make_float2(v.z, v.w));
    float2 f0 = __bfloat1622float2(h0), f1 = __bfloat1622float2(h1);
    __nv_bfloat162 l0 = __float22bfloat162_rn(make_float2(v.x - f0.x, v.y - f0.y));
    __nv_bfloat162 l1 = __float22bfloat162_rn(make_float2(v.z - f1.x, v.w - f1.y));
    h = make_uint2(*(uint32_t*)&h0, *(uint32_t*)&h1);
    l = make_uint2(*(uint32_t*)&l0, *(uint32_t*)&l1);
}
__device__ __forceinline__ void split2(float v0, float v1, uint32_t& h, uint32_t& l) {
    __nv_bfloat162 hb = __float22bfloat162_rn(make_float2(v0, v1));
    float2 hf = __bfloat1622float2(hb);
    __nv_bfloat162 lb = __float22bfloat162_rn(make_float2(v0 - hf.x, v1 - hf.y));
    h = *(uint32_t*)&hb;
    l = *(uint32_t*)&lb;
}

// ===========================================================================
// Elementwise fp32 -> bf16 hi/lo split (weights)
// ===========================================================================
__global__ void split_kernel(const float* __restrict__ in,
                             __nv_bfloat16* __restrict__ oh,
                             __nv_bfloat16* __restrict__ ol, size_t n4) {
    size_t stride = (size_t)gridDim.x * blockDim.x;
    for (size_t i = (size_t)blockIdx.x * blockDim.x + threadIdx.x; i < n4; i += stride) {
        float4 v = ((const float4*)in)[i];
        uint2 h, l;
        split4(v, h, l);
        ((uint2*)oh)[i] = h;
        ((uint2*)ol)[i] = l;
    }
}

// ===========================================================================
// Routing: fast gate — Wg transposed in smem, float4 x loads, fused x split.
// 256 threads = 8 warps = 8 tokens per block; 512 blocks.
// ===========================================================================
__global__ void zero_cnt_kernel() {
    if (threadIdx.x < NE) g_cnt[threadIdx.x] = 0;
}

__global__ void __launch_bounds__(256)
gate_kernel(const float* __restrict__ x,
            const float* __restrict__ Wg,
            const float* __restrict__ bg,
            float* __restrict__ logits_out,
            int write_logits) {
    __shared__ float s_wgT[NE][DM];   // 32 KB, transposed gate weights

    int tid  = threadIdx.x;
    int lane = tid & 31, w = tid >> 5;

    // load Wg [DM][NE] -> s_wgT [NE][DM]
    for (int i = tid; i < DM * NE; i += 256) {
        int d = i >> 3, e = i & 7;
        s_wgT[e][d] = Wg[i];
    }
    __syncthreads();

    int t = blockIdx.x * 8 + w;
    const float* xr = x + (size_t)t * DM;

    float acc[NE];
#pragma unroll
    for (int e = 0; e < NE; e++) acc[e] = 0.0f;

#pragma unroll
    for (int i = 0; i < 8; i++) {
        int d4 = i * 32 + lane;            // float4 index within row
        float4 xv = ((const float4*)xr)[d4];
        // fused x hi/lo split
        uint2 h, l;
        split4(xv, h, l);
        ((uint2*)(g_x_hi + (size_t)t * DM))[d4] = h;
        ((uint2*)(g_x_lo + (size_t)t * DM))[d4] = l;
#pragma unroll
        for (int e = 0; e < NE; e++) {
            float4 wv = ((const float4*)&s_wgT[e][0])[d4];
            acc[e] += xv.x * wv.x + xv.y * wv.y + xv.z * wv.z + xv.w * wv.w;
        }
    }
#pragma unroll
    for (int e = 0; e < NE; e++)
#pragma unroll
        for (int o = 16; o > 0; o >>= 1)
            acc[e] += __shfl_xor_sync(0xffffffffu, acc[e], o);

    if (lane == 0) {
#pragma unroll
        for (int e = 0; e < NE; e++) acc[e] += bg[e];
        if (write_logits)
#pragma unroll
            for (int e = 0; e < NE; e++)
                logits_out[(size_t)t * NE + e] = acc[e];
        int i0 = 0; float v0 = acc[0];
#pragma unroll
        for (int e = 1; e < NE; e++) if (acc[e] > v0) { v0 = acc[e]; i0 = e; }
        int i1 = -1; float v1 = -INFINITY;
#pragma unroll
        for (int e = 0; e < NE; e++) {
            if (e == i0) continue;
            if (acc[e] > v1) { v1 = acc[e]; i1 = e; }
        }
        float ew  = expf(v1 - v0);
        float inv = 1.0f / (1.0f + ew);

        int s0 = atomicAdd(&g_cnt[i0], 1);
        g_tok[i0 * TT + s0] = t;
        int s1 = atomicAdd(&g_cnt[i1], 1);
        g_tok[i1 * TT + s1] = t;

        g_te[2*t]   = i0; g_ts[2*t]   = s0; g_tw[2*t]   = inv;
        g_te[2*t+1] = i1; g_ts[2*t+1] = s1; g_tw[2*t+1] = ew * inv;
    }
}

__global__ void prefix_kernel() {
    if (threadIdx.x == 0) {
        int s = 0;
#pragma unroll
        for (int e = 0; e < NE; e++) { g_base[e] = s; s += g_cnt[e]; }
    }
}

// ===========================================================================
// GEMM core: 128x128 CTA tile, BK=32, 8 warps (2x4), warp tile 64x32,
// 2-stage cp.async, bf16 hi/lo 3-pass mma, 2 CTAs/SM.
// ===========================================================================
struct TilePtrs {
    const __nv_bfloat16 *ah0, *al0, *ah1, *al1;  // 2 A chunks / thread
    uint32_t asz0, asz1;
    const __nv_bfloat16 *bh0, *bl0, *bh1, *bl1;  // 2 B chunks / thread
    int aStep, bStep;
    uint32_t aDst0, aDst1, bDst0, bDst1;
};

__device__ __forceinline__ void issue_tile(uint32_t sb, int stage, const TilePtrs& tp, int kt) {
    uint32_t s = sb + stage * STAGE_BYTES;
    int ao = kt * tp.aStep;
    int bo = kt * tp.bStep;
    cp16(s + AH_OFF + tp.aDst0, tp.ah0 + ao, tp.asz0);
    cp16(s + AL_OFF + tp.aDst0, tp.al0 + ao, tp.asz0);
    cp16(s + AH_OFF + tp.aDst1, tp.ah1 + ao, tp.asz1);
    cp16(s + AL_OFF + tp.aDst1, tp.al1 + ao, tp.asz1);
    cp16(s + BH_OFF + tp.bDst0, tp.bh0 + bo, 16);
    cp16(s + BL_OFF + tp.bDst0, tp.bl0 + bo, 16);
    cp16(s + BH_OFF + tp.bDst1, tp.bh1 + bo, 16);
    cp16(s + BL_OFF + tp.bDst1, tp.bl1 + bo, 16);
    CP_COMMIT();
}

template <int NC>
__device__ __forceinline__ void gemm_core(uint32_t sb, const TilePtrs& tp,
                                          float cacc[4][4][4],
                                          uint32_t aOff, uint32_t bOff) {
    issue_tile(sb, 0, tp, 0);
    issue_tile(sb, 1, tp, 1);
#pragma unroll 1
    for (int kt = 0; kt < NC; kt++) {
        if (kt + 1 < NC) { CP_WAIT(1); } else { CP_WAIT(0); }
        __syncthreads();
        uint32_t s = sb + (kt & 1) * STAGE_BYTES;
#pragma unroll
        for (int k16 = 0; k16 < 2; k16++) {
            uint32_t ah[4][4], al[4][4];
#pragma unroll
            for (int mi = 0; mi < 4; mi++) {
                ldsm_x4(ah[mi], s + AH_OFF + aOff + mi * 1280 + k16 * 32);
                ldsm_x4(al[mi], s + AL_OFF + aOff + mi * 1280 + k16 * 32);
            }
#pragma unroll
            for (int ni = 0; ni < 4; ni++) {
                uint32_t bh[2], bl[2];
                ldsm_x2t(bh, s + BH_OFF + bOff + ni * 16 + k16 * 4352);
                ldsm_x2t(bl, s + BL_OFF + bOff + ni * 16 + k16 * 4352);
#pragma unroll
                for (int mi = 0; mi < 4; mi++) mma16816(cacc[mi][ni], ah[mi], bh);
#pragma unroll
                for (int mi = 0; mi < 4; mi++) mma16816(cacc[mi][ni], ah[mi], bl);
#pragma unroll
                for (int mi = 0; mi < 4; mi++) mma16816(cacc[mi][ni], al[mi], bh);
            }
        }
        __syncthreads();
        if (kt + 2 < NC) issue_tile(sb, kt & 1, tp, kt + 2);
    }
}

// warp layout: 8 warps as (wm, wn) = (wid>>2, wid&3); warp tile 64x32.
__device__ __forceinline__ uint32_t calc_aoff(int wm, int lane) {
    return (uint32_t)(wm * 64 + (lane & 7) + ((lane >> 3) & 1) * 8) * 80
         + (lane >> 4) * 16;
}
__device__ __forceinline__ uint32_t calc_boff(int wn, int lane) {
    return (uint32_t)(lane & 15) * 272 + wn * 64;
}

// ===========================================================================
// GEMM1: h[base+r] = relu( x[tok[r]] @ W1[e] + b1[e] )
// ===========================================================================
__global__ void __launch_bounds__(NTHREADS, 2)
moe_gemm1(const float* __restrict__ b1) {
    int e   = blockIdx.z;
    int cnt = g_cnt[e];
    int rb  = blockIdx.y * BM;
    if (rb >= cnt) return;
    int nb   = blockIdx.x * BN;
    int base = g_base[e];

    extern __shared__ __align__(128) char smem[];
    uint32_t sb = smem_u32(smem);

    int tid  = threadIdx.x;
    int lane = tid & 31, wid = tid >> 5;
    int wm = wid >> 2, wn = wid & 3;

    TilePtrs tp;
    {
        // A: 512 16B chunks (128 rows x 4 segs), 2 per thread
        int c0 = tid,        r0 = c0 >> 2, sg0 = c0 & 3;
        int c1 = tid + 256,  r1 = c1 >> 2, sg1 = c1 & 3;
        bool v0 = (rb + r0) < cnt, v1 = (rb + r1) < cnt;
        int t0 = g_tok[e * TT + (v0 ? rb + r0 : 0)];
        int t1 = g_tok[e * TT + (v1 ? rb + r1 : 0)];
        tp.ah0 = g_x_hi + (size_t)t0 * DM + sg0 * 8;
        tp.al0 = g_x_lo + (size_t)t0 * DM + sg0 * 8;
        tp.ah1 = g_x_hi + (size_t)t1 * DM + sg1 * 8;
        tp.al1 = g_x_lo + (size_t)t1 * DM + sg1 * 8;
        tp.asz0 = v0 ? 16 : 0;
        tp.asz1 = v1 ? 16 : 0;
        tp.aDst0 = (uint32_t)r0 * 80 + sg0 * 16;
        tp.aDst1 = (uint32_t)r1 * 80 + sg1 * 16;
        tp.aStep = BK;
        // B: 512 chunks (32 k-rows x 16 segs), 2 per thread
        int kc0 = tid,       kr0 = kc0 >> 4, bs0 = kc0 & 15;
        int kc1 = tid + 256, kr1 = kc1 >> 4, bs1 = kc1 & 15;
        size_t wbase = (size_t)e * DM * DH;
        tp.bh0 = g_w1_hi + wbase + (size_t)kr0 * DH + nb + bs0 * 8;
        tp.bl0 = g_w1_lo + wbase + (size_t)kr0 * DH + nb + bs0 * 8;
        tp.bh1 = g_w1_hi + wbase + (size_t)kr1 * DH + nb + bs1 * 8;
        tp.bl1 = g_w1_lo + wbase + (size_t)kr1 * DH + nb + bs1 * 8;
        tp.bDst0 = (uint32_t)kr0 * 272 + bs0 * 16;
        tp.bDst1 = (uint32_t)kr1 * 272 + bs1 * 16;
        tp.bStep = BK * DH;
    }

    uint32_t aOff = calc_aoff(wm, lane);
    uint32_t bOff = calc_boff(wn, lane);

    float cacc[4][4][4];
#pragma unroll
    for (int mi = 0; mi < 4; mi++)
#pragma unroll
        for (int ni = 0; ni < 4; ni++)
#pragma unroll
            for (int q = 0; q < 4; q++) cacc[mi][ni][q] = 0.0f;

    gemm_core<DM / BK>(sb, tp, cacc, aOff, bOff);

    const float* bb = b1 + (size_t)e * DH + nb;
    int er = wm * 64 + (lane >> 2);
    int ec = wn * 32 + (lane & 3) * 2;
#pragma unroll
    for (int mi = 0; mi < 4; mi++) {
#pragma unroll
        for (int rr = 0; rr < 2; rr++) {
            int m = er + mi * 16 + rr * 8;
            if (rb + m >= cnt) continue;
            size_t rowoff = (size_t)(base + rb + m) * DH + nb;
#pragma unroll
            for (int ni = 0; ni < 4; ni++) {
                int c = ec + ni * 8;
                float v0 = cacc[mi][ni][rr * 2 + 0] + bb[c];
                float v1 = cacc[mi][ni][rr * 2 + 1] + bb[c + 1];
                v0 = v0 > 0.f ? v0 : 0.f;
                v1 = v1 > 0.f ? v1 : 0.f;
                uint32_t h, l;
                split2(v0, v1, h, l);
                *(uint32_t*)(g_h_hi + rowoff + c) = h;
                *(uint32_t*)(g_h_lo + rowoff + c) = l;
            }
        }
    }
}

// ===========================================================================
// GEMM2: yp[base+r] = h[base+r] @ W2[e] + b2[e]
// ===========================================================================
__global__ void __launch_bounds__(NTHREADS, 2)
moe_gemm2(const float* __restrict__ b2) {
    int e   = blockIdx.z;
    int cnt = g_cnt[e];
    int rb  = blockIdx.y * BM;
    if (rb >= cnt) return;
    int nb   = blockIdx.x * BN;
    int base = g_base[e];

    extern __shared__ __align__(128) char smem[];
    uint32_t sb = smem_u32(smem);

    int tid  = threadIdx.x;
    int lane = tid & 31, wid = tid >> 5;
    int wm = wid >> 2, wn = wid & 3;

    TilePtrs tp;
    {
        int c0 = tid,        r0 = c0 >> 2, sg0 = c0 & 3;
        int c1 = tid + 256,  r1 = c1 >> 2, sg1 = c1 & 3;
        size_t a0 = (size_t)(base + rb + r0) * DH + sg0 * 8;   // HPAD covers tails
        size_t a1 = (size_t)(base + rb + r1) * DH + sg1 * 8;
        tp.ah0 = g_h_hi + a0; tp.al0 = g_h_lo + a0;
        tp.ah1 = g_h_hi + a1; tp.al1 = g_h_lo + a1;
        tp.asz0 = 16; tp.asz1 = 16;
        tp.aDst0 = (uint32_t)r0 * 80 + sg0 * 16;
        tp.aDst1 = (uint32_t)r1 * 80 + sg1 * 16;
        tp.aStep = BK;
        int kc0 = tid,       kr0 = kc0 >> 4, bs0 = kc0 & 15;
        int kc1 = tid + 256, kr1 = kc1 >> 4, bs1 = kc1 & 15;
        size_t wbase = (size_t)e * DH * DM;
        tp.bh0 = g_w2_hi + wbase + (size_t)kr0 * DM + nb + bs0 * 8;
        tp.bl0 = g_w2_lo + wbase + (size_t)kr0 * DM + nb + bs0 * 8;
        tp.bh1 = g_w2_hi + wbase + (size_t)kr1 * DM + nb + bs1 * 8;
        tp.bl1 = g_w2_lo + wbase + (size_t)kr1 * DM + nb + bs1 * 8;
        tp.bDst0 = (uint32_t)kr0 * 272 + bs0 * 16;
        tp.bDst1 = (uint32_t)kr1 * 272 + bs1 * 16;
        tp.bStep = BK * DM;
    }

    uint32_t aOff = calc_aoff(wm, lane);
    uint32_t bOff = calc_boff(wn, lane);

    float cacc[4][4][4];
#pragma unroll
    for (int mi = 0; mi < 4; mi++)
#pragma unroll
        for (int ni = 0; ni < 4; ni++)
#pragma unroll
            for (int q = 0; q < 4; q++) cacc[mi][ni][q] = 0.0f;

    gemm_core<DH / BK>(sb, tp, cacc, aOff, bOff);

    const float* bb = b2 + (size_t)e * DM + nb;
    int er = wm * 64 + (lane >> 2);
    int ec = wn * 32 + (lane & 3) * 2;
#pragma unroll
    for (int mi = 0; mi < 4; mi++) {
#pragma unroll
        for (int rr = 0; rr < 2; rr++) {
            int m = er + mi * 16 + rr * 8;
            if (rb + m >= cnt) continue;
            float* yrow = g_yp + (size_t)(base + rb + m) * DM + nb;
#pragma unroll
            for (int ni = 0; ni < 4; ni++) {
                int c = ec + ni * 8;
                float2 o;
                o.x = cacc[mi][ni][rr * 2 + 0] + bb[c];
                o.y = cacc[mi][ni][rr * 2 + 1] + bb[c + 1];
                *(float2*)(yrow + c) = o;
            }
        }
    }
}

// ===========================================================================
// combine: out[t] = w0*yp[r0] + w1*yp[r1]
// ===========================================================================
__global__ void combine_kernel(float* __restrict__ out) {
    int t = blockIdx.x;
    int c = threadIdx.x;
    int e0 = g_te[2*t],   e1 = g_te[2*t+1];
    int r0 = g_base[e0] + g_ts[2*t];
    int r1 = g_base[e1] + g_ts[2*t+1];
    float w0 = g_tw[2*t], w1 = g_tw[2*t+1];
    float4 a = ((const float4*)(g_yp + (size_t)r0 * DM))[c];
    float4 b = ((const float4*)(g_yp + (size_t)r1 * DM))[c];
    float4 o;
    o.x = w0 * a.x + w1 * b.x;
    o.y = w0 * a.y + w1 * b.y;
    o.z = w0 * a.z + w1 * b.z;
    o.w = w0 * a.w + w1 * b.w;
    ((float4*)(out + (size_t)t * DM))[c] = o;
}

// ===========================================================================
// Launch
// ===========================================================================
extern "C" void kernel_launch(void* const* d_in, const int* in_sizes, int n_in,
                              void* d_out, int out_size) {
    const float* x  = (const float*)d_in[0];
    const float* Wg = (const float*)d_in[1];
    const float* bg = (const float*)d_in[2];
    const float* W1 = (const float*)d_in[3];
    const float* b1 = (const float*)d_in[4];
    const float* W2 = (const float*)d_in[5];
    const float* b2 = (const float*)d_in[6];

    float* out_y = (float*)d_out;
    int write_logits = (out_size >= TT * (DM + NE)) ? 1 : 0;
    float* logits = out_y + (size_t)TT * DM;

    cudaFuncSetAttribute(moe_gemm1, cudaFuncAttributeMaxDynamicSharedMemorySize, SMEM_BYTES);
    cudaFuncSetAttribute(moe_gemm2, cudaFuncAttributeMaxDynamicSharedMemorySize, SMEM_BYTES);

    __nv_bfloat16 *w1h, *w1l, *w2h, *w2l;
    cudaGetSymbolAddress((void**)&w1h, g_w1_hi);
    cudaGetSymbolAddress((void**)&w1l, g_w1_lo);
    cudaGetSymbolAddress((void**)&w2h, g_w2_hi);
    cudaGetSymbolAddress((void**)&w2l, g_w2_lo);

    zero_cnt_kernel<<<1, 32>>>();
    split_kernel<<<8192, 256>>>(W1, w1h, w1l, (size_t)NE * DM * DH / 4);
    split_kernel<<<8192, 256>>>(W2, w2h, w2l, (size_t)NE * DH * DM / 4);
    gate_kernel<<<TT / 8, 256>>>(x, Wg, bg, logits, write_logits);
    prefix_kernel<<<1, 32>>>();

    moe_gemm1<<<dim3(DH / BN, TT / BM, NE), NTHREADS, SMEM_BYTES>>>(b1);
    moe_gemm2<<<dim3(DM / BN, TT / BM, NE), NTHREADS, SMEM_BYTES>>>(b2);

    combine_kernel<<<TT, DM / 4>>>(out_y);
}

// round 7
// speedup vs baseline: 1.5771x; 1.4081x over previous
#include <cuda_runtime.h>
#include <cuda_fp16.h>
#include <cstdint>
#include <math.h>

// Problem constants (MoELayer_76433237999752)
#define TT 4096      // tokens = B*S
#define DM 1024      // d_model
#define DH 4096      // d_hidden
#define NE 8         // experts
#define RTOT (TT*2)  // total routed rows (top-2)
#define HPAD 128     // row padding so GEMM2 A-tile reads never go OOB

// GEMM tiling: CTA tile 128x128, BK=32, 256 threads = 8 warps (2 x 4),
// warp tile 64x32, 3-stage cp.async, 2 CTAs/SM, fp16 2-pass emulation.
#define BM 128
#define BN 128
#define BK 32
#define NTHREADS 256
// SMEM stage layout (bytes): A[128*80] Bh[32*272] Bl[32*272]
#define AH_OFF 0
#define BH_OFF 10240
#define BL_OFF 18944
#define STAGE_BYTES 27648
#define NSTAGE 3
#define SMEM_BYTES (STAGE_BYTES * NSTAGE)   // 82944

// ===========================================================================
// Device-global scratch
// ===========================================================================
__device__ int    g_cnt [NE];
__device__ int    g_base[NE];
__device__ int    g_tok [NE * TT];
__device__ int    g_te  [TT * 2];
__device__ int    g_ts  [TT * 2];
__device__ float  g_tw  [TT * 2];
__device__ __half g_x   [(size_t)TT * DM];            // x in fp16 (hi only)
__device__ __half g_w1_hi[(size_t)NE * DM * DH];
__device__ __half g_w1_lo[(size_t)NE * DM * DH];
__device__ __half g_w2_hi[(size_t)NE * DH * DM];
__device__ __half g_w2_lo[(size_t)NE * DH * DM];
__device__ __half g_h   [(size_t)(RTOT + HPAD) * DH]; // hidden, fp16
__device__ float  g_yp  [(size_t)RTOT * DM];

// ===========================================================================
// PTX helpers (plain sm_80-era — nothing "a"-gated)
// ===========================================================================
__device__ __forceinline__ uint32_t smem_u32(const void* p) {
    uint32_t a;
    asm("{ .reg .u64 t; cvta.to.shared.u64 t, %1; cvt.u32.u64 %0, t; }" : "=r"(a) : "l"(p));
    return a;
}
__device__ __forceinline__ void ldsm_x4(uint32_t* r, uint32_t addr) {
    asm volatile("ldmatrix.sync.aligned.m8n8.x4.shared.b16 {%0,%1,%2,%3}, [%4];"
                 : "=r"(r[0]), "=r"(r[1]), "=r"(r[2]), "=r"(r[3]) : "r"(addr));
}
__device__ __forceinline__ void ldsm_x2t(uint32_t* r, uint32_t addr) {
    asm volatile("ldmatrix.sync.aligned.m8n8.x2.trans.shared.b16 {%0,%1}, [%2];"
                 : "=r"(r[0]), "=r"(r[1]) : "r"(addr));
}
__device__ __forceinline__ void mma16816(float* c, const uint32_t* a, const uint32_t* b) {
    asm volatile("mma.sync.aligned.m16n8k16.row.col.f32.f16.f16.f32 "
                 "{%0,%1,%2,%3}, {%4,%5,%6,%7}, {%8,%9}, {%0,%1,%2,%3};"
                 : "+f"(c[0]), "+f"(c[1]), "+f"(c[2]), "+f"(c[3])
                 : "r"(a[0]), "r"(a[1]), "r"(a[2]), "r"(a[3]), "r"(b[0]), "r"(b[1]));
}
__device__ __forceinline__ void cp16(uint32_t dst, const void* src, uint32_t sz) {
    asm volatile("cp.async.cg.shared.global [%0], [%1], 16, %2;"
                 :: "r"(dst), "l"(src), "r"(sz) : "memory");
}
#define CP_COMMIT() asm volatile("cp.async.commit_group;" ::: "memory")
#define CP_WAIT(n)  asm volatile("cp.async.wait_group %0;" :: "n"(n) : "memory")

// fp32 -> fp16 hi/lo split (4 elems)
__device__ __forceinline__ void split4h(float4 v, uint2& h, uint2& l) {
    __half2 h0 = __float22half2_rn(make_float2(v.x, v.y));
    __half2 h1 = __float22half2_rn(make_float2(v.z, v.w));
    float2 f0 = __half22float2(h0), f1 = __half22float2(h1);
    __half2 l0 = __float22half2_rn(make_float2(v.x - f0.x, v.y - f0.y));
    __half2 l1 = __float22half2_rn(make_float2(v.z - f1.x, v.w - f1.y));
    h = make_uint2(*(uint32_t*)&h0, *(uint32_t*)&h1);
    l = make_uint2(*(uint32_t*)&l0, *(uint32_t*)&l1);
}
// fp32x4 -> fp16x4 (hi only)
__device__ __forceinline__ uint2 pack4h(float4 v) {
    __half2 h0 = __float22half2_rn(make_float2(v.x, v.y));
    __half2 h1 = __float22half2_rn(make_float2(v.z, v.w));
    return make_uint2(*(uint32_t*)&h0, *(uint32_t*)&h1);
}

// ===========================================================================
// Weight split: fp32 -> fp16 hi + fp16 lo
// ===========================================================================
__global__ void split_kernel(const float* __restrict__ in,
                             __half* __restrict__ oh,
                             __half* __restrict__ ol, size_t n4) {
    size_t stride = (size_t)gridDim.x * blockDim.x;
    for (size_t i = (size_t)blockIdx.x * blockDim.x + threadIdx.x; i < n4; i += stride) {
        float4 v = ((const float4*)in)[i];
        uint2 h, l;
        split4h(v, h, l);
        ((uint2*)oh)[i] = h;
        ((uint2*)ol)[i] = l;
    }
}

// ===========================================================================
// Routing: smem-tiled gate, fused x fp16 conversion.
// ===========================================================================
__global__ void zero_cnt_kernel() {
    if (threadIdx.x < NE) g_cnt[threadIdx.x] = 0;
}

__global__ void __launch_bounds__(256)
gate_kernel(const float* __restrict__ x,
            const float* __restrict__ Wg,
            const float* __restrict__ bg,
            float* __restrict__ logits_out,
            int write_logits) {
    __shared__ float s_wgT[NE][DM];   // 32 KB, transposed gate weights

    int tid  = threadIdx.x;
    int lane = tid & 31, w = tid >> 5;

    for (int i = tid; i < DM * NE; i += 256) {
        int d = i >> 3, e = i & 7;
        s_wgT[e][d] = Wg[i];
    }
    __syncthreads();

    int t = blockIdx.x * 8 + w;
    const float* xr = x + (size_t)t * DM;

    float acc[NE];
#pragma unroll
    for (int e = 0; e < NE; e++) acc[e] = 0.0f;

#pragma unroll
    for (int i = 0; i < 8; i++) {
        int d4 = i * 32 + lane;            // float4 index within row
        float4 xv = ((const float4*)xr)[d4];
        ((uint2*)(g_x + (size_t)t * DM))[d4] = pack4h(xv);
#pragma unroll
        for (int e = 0; e < NE; e++) {
            float4 wv = ((const float4*)&s_wgT[e][0])[d4];
            acc[e] += xv.x * wv.x + xv.y * wv.y + xv.z * wv.z + xv.w * wv.w;
        }
    }
#pragma unroll
    for (int e = 0; e < NE; e++)
#pragma unroll
        for (int o = 16; o > 0; o >>= 1)
            acc[e] += __shfl_xor_sync(0xffffffffu, acc[e], o);

    if (lane == 0) {
#pragma unroll
        for (int e = 0; e < NE; e++) acc[e] += bg[e];
        if (write_logits)
#pragma unroll
            for (int e = 0; e < NE; e++)
                logits_out[(size_t)t * NE + e] = acc[e];
        int i0 = 0; float v0 = acc[0];
#pragma unroll
        for (int e = 1; e < NE; e++) if (acc[e] > v0) { v0 = acc[e]; i0 = e; }
        int i1 = -1; float v1 = -INFINITY;
#pragma unroll
        for (int e = 0; e < NE; e++) {
            if (e == i0) continue;
            if (acc[e] > v1) { v1 = acc[e]; i1 = e; }
        }
        float ew  = expf(v1 - v0);
        float inv = 1.0f / (1.0f + ew);

        int s0 = atomicAdd(&g_cnt[i0], 1);
        g_tok[i0 * TT + s0] = t;
        int s1 = atomicAdd(&g_cnt[i1], 1);
        g_tok[i1 * TT + s1] = t;

        g_te[2*t]   = i0; g_ts[2*t]   = s0; g_tw[2*t]   = inv;
        g_te[2*t+1] = i1; g_ts[2*t+1] = s1; g_tw[2*t+1] = ew * inv;
    }
}

__global__ void prefix_kernel() {
    if (threadIdx.x == 0) {
        int s = 0;
#pragma unroll
        for (int e = 0; e < NE; e++) { g_base[e] = s; s += g_cnt[e]; }
    }
}

// ===========================================================================
// GEMM core: 128x128 CTA tile, BK=32, 8 warps (2x4), warp tile 64x32,
// 3-stage cp.async, fp16 2-pass mma:  C = A_f16 * (B_hi + B_lo)
// ===========================================================================
struct TilePtrs {
    const __half *a0, *a1;            // 2 A chunks / thread
    uint32_t asz0, asz1;
    const __half *bh0, *bl0, *bh1, *bl1;   // 2 B chunks / thread (hi & lo)
    int aStep, bStep;
    uint32_t aDst0, aDst1, bDst0, bDst1;
};

__device__ __forceinline__ void issue_tile(uint32_t sb, int stage, const TilePtrs& tp, int kt) {
    uint32_t s = sb + stage * STAGE_BYTES;
    int ao = kt * tp.aStep;
    int bo = kt * tp.bStep;
    cp16(s + AH_OFF + tp.aDst0, tp.a0 + ao, tp.asz0);
    cp16(s + AH_OFF + tp.aDst1, tp.a1 + ao, tp.asz1);
    cp16(s + BH_OFF + tp.bDst0, tp.bh0 + bo, 16);
    cp16(s + BH_OFF + tp.bDst1, tp.bh1 + bo, 16);
    cp16(s + BL_OFF + tp.bDst0, tp.bl0 + bo, 16);
    cp16(s + BL_OFF + tp.bDst1, tp.bl1 + bo, 16);
    CP_COMMIT();
}

template <int NC>
__device__ __forceinline__ void gemm_core(uint32_t sb, const TilePtrs& tp,
                                          float cacc[4][4][4],
                                          uint32_t aOff, uint32_t bOff) {
    issue_tile(sb, 0, tp, 0);
    issue_tile(sb, 1, tp, 1);
#pragma unroll 1
    for (int kt = 0; kt < NC; kt++) {
        if (kt + 1 < NC) { CP_WAIT(1); } else { CP_WAIT(0); }
        __syncthreads();
        if (kt + 2 < NC) issue_tile(sb, (kt + 2) % NSTAGE, tp, kt + 2);
        uint32_t s = sb + (kt % NSTAGE) * STAGE_BYTES;
#pragma unroll
        for (int k16 = 0; k16 < 2; k16++) {
            uint32_t ah[4][4];
#pragma unroll
            for (int mi = 0; mi < 4; mi++)
                ldsm_x4(ah[mi], s + AH_OFF + aOff + mi * 1280 + k16 * 32);
#pragma unroll
            for (int ni = 0; ni < 4; ni++) {
                uint32_t bh[2], bl[2];
                ldsm_x2t(bh, s + BH_OFF + bOff + ni * 16 + k16 * 4352);
                ldsm_x2t(bl, s + BL_OFF + bOff + ni * 16 + k16 * 4352);
#pragma unroll
                for (int mi = 0; mi < 4; mi++) mma16816(cacc[mi][ni], ah[mi], bh);
#pragma unroll
                for (int mi = 0; mi < 4; mi++) mma16816(cacc[mi][ni], ah[mi], bl);
            }
        }
    }
}

// warp layout: 8 warps as (wm, wn) = (wid>>2, wid&3); warp tile 64x32.
__device__ __forceinline__ uint32_t calc_aoff(int wm, int lane) {
    return (uint32_t)(wm * 64 + (lane & 7) + ((lane >> 3) & 1) * 8) * 80
         + (lane >> 4) * 16;
}
__device__ __forceinline__ uint32_t calc_boff(int wn, int lane) {
    return (uint32_t)(lane & 15) * 272 + wn * 64;
}

// ===========================================================================
// GEMM1: h[base+r] = relu( x[tok[r]] @ W1[e] + b1[e] )  (h stored fp16)
// ===========================================================================
__global__ void __launch_bounds__(NTHREADS, 2)
moe_gemm1(const float* __restrict__ b1) {
    int e   = blockIdx.z;
    int cnt = g_cnt[e];
    int rb  = blockIdx.y * BM;
    if (rb >= cnt) return;
    int nb   = blockIdx.x * BN;
    int base = g_base[e];

    extern __shared__ __align__(128) char smem[];
    uint32_t sb = smem_u32(smem);

    int tid  = threadIdx.x;
    int lane = tid & 31, wid = tid >> 5;
    int wm = wid >> 2, wn = wid & 3;

    TilePtrs tp;
    {
        // A: 512 16B chunks (128 rows x 4 segs), 2 per thread
        int c0 = tid,        r0 = c0 >> 2, sg0 = c0 & 3;
        int c1 = tid + 256,  r1 = c1 >> 2, sg1 = c1 & 3;
        bool v0 = (rb + r0) < cnt, v1 = (rb + r1) < cnt;
        int t0 = g_tok[e * TT + (v0 ? rb + r0 : 0)];
        int t1 = g_tok[e * TT + (v1 ? rb + r1 : 0)];
        tp.a0 = g_x + (size_t)t0 * DM + sg0 * 8;
        tp.a1 = g_x + (size_t)t1 * DM + sg1 * 8;
        tp.asz0 = v0 ? 16 : 0;
        tp.asz1 = v1 ? 16 : 0;
        tp.aDst0 = (uint32_t)r0 * 80 + sg0 * 16;
        tp.aDst1 = (uint32_t)r1 * 80 + sg1 * 16;
        tp.aStep = BK;
        // B: 512 chunks (32 k-rows x 16 segs), 2 per thread
        int kc0 = tid,       kr0 = kc0 >> 4, bs0 = kc0 & 15;
        int kc1 = tid + 256, kr1 = kc1 >> 4, bs1 = kc1 & 15;
        size_t wbase = (size_t)e * DM * DH;
        tp.bh0 = g_w1_hi + wbase + (size_t)kr0 * DH + nb + bs0 * 8;
        tp.bl0 = g_w1_lo + wbase + (size_t)kr0 * DH + nb + bs0 * 8;
        tp.bh1 = g_w1_hi + wbase + (size_t)kr1 * DH + nb + bs1 * 8;
        tp.bl1 = g_w1_lo + wbase + (size_t)kr1 * DH + nb + bs1 * 8;
        tp.bDst0 = (uint32_t)kr0 * 272 + bs0 * 16;
        tp.bDst1 = (uint32_t)kr1 * 272 + bs1 * 16;
        tp.bStep = BK * DH;
    }

    uint32_t aOff = calc_aoff(wm, lane);
    uint32_t bOff = calc_boff(wn, lane);

    float cacc[4][4][4];
#pragma unroll
    for (int mi = 0; mi < 4; mi++)
#pragma unroll
        for (int ni = 0; ni < 4; ni++)
#pragma unroll
            for (int q = 0; q < 4; q++) cacc[mi][ni][q] = 0.0f;

    gemm_core<DM / BK>(sb, tp, cacc, aOff, bOff);

    const float* bb = b1 + (size_t)e * DH + nb;
    int er = wm * 64 + (lane >> 2);
    int ec = wn * 32 + (lane & 3) * 2;
#pragma unroll
    for (int mi = 0; mi < 4; mi++) {
#pragma unroll
        for (int rr = 0; rr < 2; rr++) {
            int m = er + mi * 16 + rr * 8;
            if (rb + m >= cnt) continue;
            size_t rowoff = (size_t)(base + rb + m) * DH + nb;
#pragma unroll
            for (int ni = 0; ni < 4; ni++) {
                int c = ec + ni * 8;
                float v0 = cacc[mi][ni][rr * 2 + 0] + bb[c];
                float v1 = cacc[mi][ni][rr * 2 + 1] + bb[c + 1];
                v0 = v0 > 0.f ? v0 : 0.f;
                v1 = v1 > 0.f ? v1 : 0.f;
                __half2 hv = __float22half2_rn(make_float2(v0, v1));
                *(uint32_t*)(g_h + rowoff + c) = *(uint32_t*)&hv;
            }
        }
    }
}

// ===========================================================================
// GEMM2: yp[base+r] = h[base+r] @ W2[e] + b2[e]
// ===========================================================================
__global__ void __launch_bounds__(NTHREADS, 2)
moe_gemm2(const float* __restrict__ b2) {
    int e   = blockIdx.z;
    int cnt = g_cnt[e];
    int rb  = blockIdx.y * BM;
    if (rb >= cnt) return;
    int nb   = blockIdx.x * BN;
    int base = g_base[e];

    extern __shared__ __align__(128) char smem[];
    uint32_t sb = smem_u32(smem);

    int tid  = threadIdx.x;
    int lane = tid & 31, wid = tid >> 5;
    int wm = wid >> 2, wn = wid & 3;

    TilePtrs tp;
    {
        int c0 = tid,        r0 = c0 >> 2, sg0 = c0 & 3;
        int c1 = tid + 256,  r1 = c1 >> 2, sg1 = c1 & 3;
        tp.a0 = g_h + (size_t)(base + rb + r0) * DH + sg0 * 8;  // HPAD covers tails
        tp.a1 = g_h + (size_t)(base + rb + r1) * DH + sg1 * 8;
        tp.asz0 = 16; tp.asz1 = 16;
        tp.aDst0 = (uint32_t)r0 * 80 + sg0 * 16;
        tp.aDst1 = (uint32_t)r1 * 80 + sg1 * 16;
        tp.aStep = BK;
        int kc0 = tid,       kr0 = kc0 >> 4, bs0 = kc0 & 15;
        int kc1 = tid + 256, kr1 = kc1 >> 4, bs1 = kc1 & 15;
        size_t wbase = (size_t)e * DH * DM;
        tp.bh0 = g_w2_hi + wbase + (size_t)kr0 * DM + nb + bs0 * 8;
        tp.bl0 = g_w2_lo + wbase + (size_t)kr0 * DM + nb + bs0 * 8;
        tp.bh1 = g_w2_hi + wbase + (size_t)kr1 * DM + nb + bs1 * 8;
        tp.bl1 = g_w2_lo + wbase + (size_t)kr1 * DM + nb + bs1 * 8;
        tp.bDst0 = (uint32_t)kr0 * 272 + bs0 * 16;
        tp.bDst1 = (uint32_t)kr1 * 272 + bs1 * 16;
        tp.bStep = BK * DM;
    }

    uint32_t aOff = calc_aoff(wm, lane);
    uint32_t bOff = calc_boff(wn, lane);

    float cacc[4][4][4];
#pragma unroll
    for (int mi = 0; mi < 4; mi++)
#pragma unroll
        for (int ni = 0; ni < 4; ni++)
#pragma unroll
            for (int q = 0; q < 4; q++) cacc[mi][ni][q] = 0.0f;

    gemm_core<DH / BK>(sb, tp, cacc, aOff, bOff);

    const float* bb = b2 + (size_t)e * DM + nb;
    int er = wm * 64 + (lane >> 2);
    int ec = wn * 32 + (lane & 3) * 2;
#pragma unroll
    for (int mi = 0; mi < 4; mi++) {
#pragma unroll
        for (int rr = 0; rr < 2; rr++) {
            int m = er + mi * 16 + rr * 8;
            if (rb + m >= cnt) continue;
            float* yrow = g_yp + (size_t)(base + rb + m) * DM + nb;
#pragma unroll
            for (int ni = 0; ni < 4; ni++) {
                int c = ec + ni * 8;
                float2 o;
                o.x = cacc[mi][ni][rr * 2 + 0] + bb[c];
                o.y = cacc[mi][ni][rr * 2 + 1] + bb[c + 1];
                *(float2*)(yrow + c) = o;
            }
        }
    }
}

// ===========================================================================
// combine: out[t] = w0*yp[r0] + w1*yp[r1]
// ===========================================================================
__global__ void combine_kernel(float* __restrict__ out) {
    int t = blockIdx.x;
    int c = threadIdx.x;
    int e0 = g_te[2*t],   e1 = g_te[2*t+1];
    int r0 = g_base[e0] + g_ts[2*t];
    int r1 = g_base[e1] + g_ts[2*t+1];
    float w0 = g_tw[2*t], w1 = g_tw[2*t+1];
    float4 a = ((const float4*)(g_yp + (size_t)r0 * DM))[c];
    float4 b = ((const float4*)(g_yp + (size_t)r1 * DM))[c];
    float4 o;
    o.x = w0 * a.x + w1 * b.x;
    o.y = w0 * a.y + w1 * b.y;
    o.z = w0 * a.z + w1 * b.z;
    o.w = w0 * a.w + w1 * b.w;
    ((float4*)(out + (size_t)t * DM))[c] = o;
}

// ===========================================================================
// Launch
// ===========================================================================
extern "C" void kernel_launch(void* const* d_in, const int* in_sizes, int n_in,
                              void* d_out, int out_size) {
    const float* x  = (const float*)d_in[0];
    const float* Wg = (const float*)d_in[1];
    const float* bg = (const float*)d_in[2];
    const float* W1 = (const float*)d_in[3];
    const float* b1 = (const float*)d_in[4];
    const float* W2 = (const float*)d_in[5];
    const float* b2 = (const float*)d_in[6];

    float* out_y = (float*)d_out;
    int write_logits = (out_size >= TT * (DM + NE)) ? 1 : 0;
    float* logits = out_y + (size_t)TT * DM;

    cudaFuncSetAttribute(moe_gemm1, cudaFuncAttributeMaxDynamicSharedMemorySize, SMEM_BYTES);
    cudaFuncSetAttribute(moe_gemm2, cudaFuncAttributeMaxDynamicSharedMemorySize, SMEM_BYTES);

    __half *w1h, *w1l, *w2h, *w2l;
    cudaGetSymbolAddress((void**)&w1h, g_w1_hi);
    cudaGetSymbolAddress((void**)&w1l, g_w1_lo);
    cudaGetSymbolAddress((void**)&w2h, g_w2_hi);
    cudaGetSymbolAddress((void**)&w2l, g_w2_lo);

    zero_cnt_kernel<<<1, 32>>>();
    split_kernel<<<8192, 256>>>(W1, w1h, w1l, (size_t)NE * DM * DH / 4);
    split_kernel<<<8192, 256>>>(W2, w2h, w2l, (size_t)NE * DH * DM / 4);
    gate_kernel<<<TT / 8, 256>>>(x, Wg, bg, logits, write_logits);
    prefix_kernel<<<1, 32>>>();

    moe_gemm1<<<dim3(DH / BN, TT / BM, NE), NTHREADS, SMEM_BYTES>>>(b1);
    moe_gemm2<<<dim3(DM / BN, TT / BM, NE), NTHREADS, SMEM_BYTES>>>(b2);

    combine_kernel<<<TT, DM / 4>>>(out_y);
}

// round 8
// speedup vs baseline: 2.5064x; 1.5892x over previous
#include <cuda_runtime.h>
#include <cuda_fp16.h>
#include <cstdint>
#include <math.h>

// Problem constants (MoELayer_76433237999752)
#define TT 4096      // tokens = B*S
#define DM 1024      // d_model
#define DH 4096      // d_hidden
#define NE 8         // experts
#define RTOT (TT*2)  // total routed rows (top-2)
#define HPAD 128     // row padding so GEMM2 A-tile reads never go OOB

// GEMM tiling: CTA tile 128x128, BK=32, 256 threads = 8 warps (2 x 4),
// warp tile 64x32, 3-stage cp.async, 2 CTAs/SM, single-pass fp16 mma.
#define BM 128
#define BN 128
#define BK 32
#define NTHREADS 256
// SMEM stage layout (bytes): A[128*80] B[32*272]
#define A_OFF 0
#define B_OFF 10240
#define STAGE_BYTES 18944
#define NSTAGE 3
#define SMEM_BYTES (STAGE_BYTES * NSTAGE)   // 56832

// ===========================================================================
// Device-global scratch
// ===========================================================================
__device__ int    g_cnt [NE];
__device__ int    g_base[NE];
__device__ int    g_tok [NE * TT];
__device__ int    g_te  [TT * 2];
__device__ int    g_ts  [TT * 2];
__device__ float  g_tw  [TT * 2];
__device__ __half g_x  [(size_t)TT * DM];             // x in fp16
__device__ __half g_w1 [(size_t)NE * DM * DH];        // W1 in fp16
__device__ __half g_w2 [(size_t)NE * DH * DM];        // W2 in fp16
__device__ __half g_h  [(size_t)(RTOT + HPAD) * DH];  // hidden, fp16
__device__ float  g_yp [(size_t)RTOT * DM];

// ===========================================================================
// PTX helpers (plain sm_80-era — nothing "a"-gated)
// ===========================================================================
__device__ __forceinline__ uint32_t smem_u32(const void* p) {
    uint32_t a;
    asm("{ .reg .u64 t; cvta.to.shared.u64 t, %1; cvt.u32.u64 %0, t; }" : "=r"(a) : "l"(p));
    return a;
}
__device__ __forceinline__ void ldsm_x4(uint32_t* r, uint32_t addr) {
    asm volatile("ldmatrix.sync.aligned.m8n8.x4.shared.b16 {%0,%1,%2,%3}, [%4];"
                 : "=r"(r[0]), "=r"(r[1]), "=r"(r[2]), "=r"(r[3]) : "r"(addr));
}
__device__ __forceinline__ void ldsm_x2t(uint32_t* r, uint32_t addr) {
    asm volatile("ldmatrix.sync.aligned.m8n8.x2.trans.shared.b16 {%0,%1}, [%2];"
                 : "=r"(r[0]), "=r"(r[1]) : "r"(addr));
}
__device__ __forceinline__ void mma16816(float* c, const uint32_t* a, const uint32_t* b) {
    asm volatile("mma.sync.aligned.m16n8k16.row.col.f32.f16.f16.f32 "
                 "{%0,%1,%2,%3}, {%4,%5,%6,%7}, {%8,%9}, {%0,%1,%2,%3};"
                 : "+f"(c[0]), "+f"(c[1]), "+f"(c[2]), "+f"(c[3])
                 : "r"(a[0]), "r"(a[1]), "r"(a[2]), "r"(a[3]), "r"(b[0]), "r"(b[1]));
}
__device__ __forceinline__ void cp16(uint32_t dst, const void* src, uint32_t sz) {
    asm volatile("cp.async.cg.shared.global [%0], [%1], 16, %2;"
                 :: "r"(dst), "l"(src), "r"(sz) : "memory");
}
#define CP_COMMIT() asm volatile("cp.async.commit_group;" ::: "memory")
#define CP_WAIT(n)  asm volatile("cp.async.wait_group %0;" :: "n"(n) : "memory")

// fp32x4 -> fp16x4
__device__ __forceinline__ uint2 pack4h(float4 v) {
    __half2 h0 = __float22half2_rn(make_float2(v.x, v.y));
    __half2 h1 = __float22half2_rn(make_float2(v.z, v.w));
    return make_uint2(*(uint32_t*)&h0, *(uint32_t*)&h1);
}

// ===========================================================================
// Weight convert: fp32 -> fp16
// ===========================================================================
__global__ void convert_kernel(const float* __restrict__ in,
                               __half* __restrict__ oh, size_t n4) {
    size_t stride = (size_t)gridDim.x * blockDim.x;
    for (size_t i = (size_t)blockIdx.x * blockDim.x + threadIdx.x; i < n4; i += stride) {
        ((uint2*)oh)[i] = pack4h(((const float4*)in)[i]);
    }
}

// ===========================================================================
// Routing: smem-tiled gate, fused x fp16 conversion.
// ===========================================================================
__global__ void zero_cnt_kernel() {
    if (threadIdx.x < NE) g_cnt[threadIdx.x] = 0;
}

__global__ void __launch_bounds__(256)
gate_kernel(const float* __restrict__ x,
            const float* __restrict__ Wg,
            const float* __restrict__ bg,
            float* __restrict__ logits_out,
            int write_logits) {
    __shared__ float s_wgT[NE][DM];   // 32 KB, transposed gate weights

    int tid  = threadIdx.x;
    int lane = tid & 31, w = tid >> 5;

    for (int i = tid; i < DM * NE; i += 256) {
        int d = i >> 3, e = i & 7;
        s_wgT[e][d] = Wg[i];
    }
    __syncthreads();

    int t = blockIdx.x * 8 + w;
    const float* xr = x + (size_t)t * DM;

    float acc[NE];
#pragma unroll
    for (int e = 0; e < NE; e++) acc[e] = 0.0f;

#pragma unroll
    for (int i = 0; i < 8; i++) {
        int d4 = i * 32 + lane;            // float4 index within row
        float4 xv = ((const float4*)xr)[d4];
        ((uint2*)(g_x + (size_t)t * DM))[d4] = pack4h(xv);
#pragma unroll
        for (int e = 0; e < NE; e++) {
            float4 wv = ((const float4*)&s_wgT[e][0])[d4];
            acc[e] += xv.x * wv.x + xv.y * wv.y + xv.z * wv.z + xv.w * wv.w;
        }
    }
#pragma unroll
    for (int e = 0; e < NE; e++)
#pragma unroll
        for (int o = 16; o > 0; o >>= 1)
            acc[e] += __shfl_xor_sync(0xffffffffu, acc[e], o);

    if (lane == 0) {
#pragma unroll
        for (int e = 0; e < NE; e++) acc[e] += bg[e];
        if (write_logits)
#pragma unroll
            for (int e = 0; e < NE; e++)
                logits_out[(size_t)t * NE + e] = acc[e];
        int i0 = 0; float v0 = acc[0];
#pragma unroll
        for (int e = 1; e < NE; e++) if (acc[e] > v0) { v0 = acc[e]; i0 = e; }
        int i1 = -1; float v1 = -INFINITY;
#pragma unroll
        for (int e = 0; e < NE; e++) {
            if (e == i0) continue;
            if (acc[e] > v1) { v1 = acc[e]; i1 = e; }
        }
        float ew  = expf(v1 - v0);
        float inv = 1.0f / (1.0f + ew);

        int s0 = atomicAdd(&g_cnt[i0], 1);
        g_tok[i0 * TT + s0] = t;
        int s1 = atomicAdd(&g_cnt[i1], 1);
        g_tok[i1 * TT + s1] = t;

        g_te[2*t]   = i0; g_ts[2*t]   = s0; g_tw[2*t]   = inv;
        g_te[2*t+1] = i1; g_ts[2*t+1] = s1; g_tw[2*t+1] = ew * inv;
    }
}

__global__ void prefix_kernel() {
    if (threadIdx.x == 0) {
        int s = 0;
#pragma unroll
        for (int e = 0; e < NE; e++) { g_base[e] = s; s += g_cnt[e]; }
    }
}

// ===========================================================================
// GEMM core: 128x128 CTA tile, BK=32, 8 warps (2x4), warp tile 64x32,
// 3-stage cp.async, single-pass fp16 mma:  C = A_f16 * B_f16
// ===========================================================================
struct TilePtrs {
    const __half *a0, *a1;            // 2 A chunks / thread
    uint32_t asz0, asz1;
    const __half *b0, *b1;            // 2 B chunks / thread
    int aStep, bStep;
    uint32_t aDst0, aDst1, bDst0, bDst1;
};

__device__ __forceinline__ void issue_tile(uint32_t sb, int stage, const TilePtrs& tp, int kt) {
    uint32_t s = sb + stage * STAGE_BYTES;
    int ao = kt * tp.aStep;
    int bo = kt * tp.bStep;
    cp16(s + A_OFF + tp.aDst0, tp.a0 + ao, tp.asz0);
    cp16(s + A_OFF + tp.aDst1, tp.a1 + ao, tp.asz1);
    cp16(s + B_OFF + tp.bDst0, tp.b0 + bo, 16);
    cp16(s + B_OFF + tp.bDst1, tp.b1 + bo, 16);
    CP_COMMIT();
}

template <int NC>
__device__ __forceinline__ void gemm_core(uint32_t sb, const TilePtrs& tp,
                                          float cacc[4][4][4],
                                          uint32_t aOff, uint32_t bOff) {
    issue_tile(sb, 0, tp, 0);
    issue_tile(sb, 1, tp, 1);
#pragma unroll 1
    for (int kt = 0; kt < NC; kt++) {
        if (kt + 1 < NC) { CP_WAIT(1); } else { CP_WAIT(0); }
        __syncthreads();
        if (kt + 2 < NC) issue_tile(sb, (kt + 2) % NSTAGE, tp, kt + 2);
        uint32_t s = sb + (kt % NSTAGE) * STAGE_BYTES;
#pragma unroll
        for (int k16 = 0; k16 < 2; k16++) {
            uint32_t ah[4][4];
#pragma unroll
            for (int mi = 0; mi < 4; mi++)
                ldsm_x4(ah[mi], s + A_OFF + aOff + mi * 1280 + k16 * 32);
#pragma unroll
            for (int ni = 0; ni < 4; ni++) {
                uint32_t bb[2];
                ldsm_x2t(bb, s + B_OFF + bOff + ni * 16 + k16 * 4352);
#pragma unroll
                for (int mi = 0; mi < 4; mi++) mma16816(cacc[mi][ni], ah[mi], bb);
            }
        }
    }
}

// warp layout: 8 warps as (wm, wn) = (wid>>2, wid&3); warp tile 64x32.
__device__ __forceinline__ uint32_t calc_aoff(int wm, int lane) {
    return (uint32_t)(wm * 64 + (lane & 7) + ((lane >> 3) & 1) * 8) * 80
         + (lane >> 4) * 16;
}
__device__ __forceinline__ uint32_t calc_boff(int wn, int lane) {
    return (uint32_t)(lane & 15) * 272 + wn * 64;
}

// ===========================================================================
// GEMM1: h[base+r] = relu( x[tok[r]] @ W1[e] + b1[e] )  (h stored fp16)
// ===========================================================================
__global__ void __launch_bounds__(NTHREADS, 2)
moe_gemm1(const float* __restrict__ b1) {
    int e   = blockIdx.z;
    int cnt = g_cnt[e];
    int rb  = blockIdx.y * BM;
    if (rb >= cnt) return;
    int nb   = blockIdx.x * BN;
    int base = g_base[e];

    extern __shared__ __align__(128) char smem[];
    uint32_t sb = smem_u32(smem);

    int tid  = threadIdx.x;
    int lane = tid & 31, wid = tid >> 5;
    int wm = wid >> 2, wn = wid & 3;

    TilePtrs tp;
    {
        // A: 512 16B chunks (128 rows x 4 segs), 2 per thread
        int c0 = tid,        r0 = c0 >> 2, sg0 = c0 & 3;
        int c1 = tid + 256,  r1 = c1 >> 2, sg1 = c1 & 3;
        bool v0 = (rb + r0) < cnt, v1 = (rb + r1) < cnt;
        int t0 = g_tok[e * TT + (v0 ? rb + r0 : 0)];
        int t1 = g_tok[e * TT + (v1 ? rb + r1 : 0)];
        tp.a0 = g_x + (size_t)t0 * DM + sg0 * 8;
        tp.a1 = g_x + (size_t)t1 * DM + sg1 * 8;
        tp.asz0 = v0 ? 16 : 0;
        tp.asz1 = v1 ? 16 : 0;
        tp.aDst0 = (uint32_t)r0 * 80 + sg0 * 16;
        tp.aDst1 = (uint32_t)r1 * 80 + sg1 * 16;
        tp.aStep = BK;
        // B: 512 chunks (32 k-rows x 16 segs), 2 per thread
        int kc0 = tid,       kr0 = kc0 >> 4, bs0 = kc0 & 15;
        int kc1 = tid + 256, kr1 = kc1 >> 4, bs1 = kc1 & 15;
        size_t wbase = (size_t)e * DM * DH;
        tp.b0 = g_w1 + wbase + (size_t)kr0 * DH + nb + bs0 * 8;
        tp.b1 = g_w1 + wbase + (size_t)kr1 * DH + nb + bs1 * 8;
        tp.bDst0 = (uint32_t)kr0 * 272 + bs0 * 16;
        tp.bDst1 = (uint32_t)kr1 * 272 + bs1 * 16;
        tp.bStep = BK * DH;
    }

    uint32_t aOff = calc_aoff(wm, lane);
    uint32_t bOff = calc_boff(wn, lane);

    float cacc[4][4][4];
#pragma unroll
    for (int mi = 0; mi < 4; mi++)
#pragma unroll
        for (int ni = 0; ni < 4; ni++)
#pragma unroll
            for (int q = 0; q < 4; q++) cacc[mi][ni][q] = 0.0f;

    gemm_core<DM / BK>(sb, tp, cacc, aOff, bOff);

    const float* bb = b1 + (size_t)e * DH + nb;
    int er = wm * 64 + (lane >> 2);
    int ec = wn * 32 + (lane & 3) * 2;
#pragma unroll
    for (int mi = 0; mi < 4; mi++) {
#pragma unroll
        for (int rr = 0; rr < 2; rr++) {
            int m = er + mi * 16 + rr * 8;
            if (rb + m >= cnt) continue;
            size_t rowoff = (size_t)(base + rb + m) * DH + nb;
#pragma unroll
            for (int ni = 0; ni < 4; ni++) {
                int c = ec + ni * 8;
                float v0 = cacc[mi][ni][rr * 2 + 0] + bb[c];
                float v1 = cacc[mi][ni][rr * 2 + 1] + bb[c + 1];
                v0 = v0 > 0.f ? v0 : 0.f;
                v1 = v1 > 0.f ? v1 : 0.f;
                __half2 hv = __float22half2_rn(make_float2(v0, v1));
                *(uint32_t*)(g_h + rowoff + c) = *(uint32_t*)&hv;
            }
        }
    }
}

// ===========================================================================
// GEMM2: yp[base+r] = h[base+r] @ W2[e] + b2[e]
// ===========================================================================
__global__ void __launch_bounds__(NTHREADS, 2)
moe_gemm2(const float* __restrict__ b2) {
    int e   = blockIdx.z;
    int cnt = g_cnt[e];
    int rb  = blockIdx.y * BM;
    if (rb >= cnt) return;
    int nb   = blockIdx.x * BN;
    int base = g_base[e];

    extern __shared__ __align__(128) char smem[];
    uint32_t sb = smem_u32(smem);

    int tid  = threadIdx.x;
    int lane = tid & 31, wid = tid >> 5;
    int wm = wid >> 2, wn = wid & 3;

    TilePtrs tp;
    {
        int c0 = tid,        r0 = c0 >> 2, sg0 = c0 & 3;
        int c1 = tid + 256,  r1 = c1 >> 2, sg1 = c1 & 3;
        tp.a0 = g_h + (size_t)(base + rb + r0) * DH + sg0 * 8;  // HPAD covers tails
        tp.a1 = g_h + (size_t)(base + rb + r1) * DH + sg1 * 8;
        tp.asz0 = 16; tp.asz1 = 16;
        tp.aDst0 = (uint32_t)r0 * 80 + sg0 * 16;
        tp.aDst1 = (uint32_t)r1 * 80 + sg1 * 16;
        tp.aStep = BK;
        int kc0 = tid,       kr0 = kc0 >> 4, bs0 = kc0 & 15;
        int kc1 = tid + 256, kr1 = kc1 >> 4, bs1 = kc1 & 15;
        size_t wbase = (size_t)e * DH * DM;
        tp.b0 = g_w2 + wbase + (size_t)kr0 * DM + nb + bs0 * 8;
        tp.b1 = g_w2 + wbase + (size_t)kr1 * DM + nb + bs1 * 8;
        tp.bDst0 = (uint32_t)kr0 * 272 + bs0 * 16;
        tp.bDst1 = (uint32_t)kr1 * 272 + bs1 * 16;
        tp.bStep = BK * DM;
    }

    uint32_t aOff = calc_aoff(wm, lane);
    uint32_t bOff = calc_boff(wn, lane);

    float cacc[4][4][4];
#pragma unroll
    for (int mi = 0; mi < 4; mi++)
#pragma unroll
        for (int ni = 0; ni < 4; ni++)
#pragma unroll
            for (int q = 0; q < 4; q++) cacc[mi][ni][q] = 0.0f;

    gemm_core<DH / BK>(sb, tp, cacc, aOff, bOff);

    const float* bb = b2 + (size_t)e * DM + nb;
    int er = wm * 64 + (lane >> 2);
    int ec = wn * 32 + (lane & 3) * 2;
#pragma unroll
    for (int mi = 0; mi < 4; mi++) {
#pragma unroll
        for (int rr = 0; rr < 2; rr++) {
            int m = er + mi * 16 + rr * 8;
            if (rb + m >= cnt) continue;
            float* yrow = g_yp + (size_t)(base + rb + m) * DM + nb;
#pragma unroll
            for (int ni = 0; ni < 4; ni++) {
                int c = ec + ni * 8;
                float2 o;
                o.x = cacc[mi][ni][rr * 2 + 0] + bb[c];
                o.y = cacc[mi][ni][rr * 2 + 1] + bb[c + 1];
                *(float2*)(yrow + c) = o;
            }
        }
    }
}

// ===========================================================================
// combine: out[t] = w0*yp[r0] + w1*yp[r1]
// ===========================================================================
__global__ void combine_kernel(float* __restrict__ out) {
    int t = blockIdx.x;
    int c = threadIdx.x;
    int e0 = g_te[2*t],   e1 = g_te[2*t+1];
    int r0 = g_base[e0] + g_ts[2*t];
    int r1 = g_base[e1] + g_ts[2*t+1];
    float w0 = g_tw[2*t], w1 = g_tw[2*t+1];
    float4 a = ((const float4*)(g_yp + (size_t)r0 * DM))[c];
    float4 b = ((const float4*)(g_yp + (size_t)r1 * DM))[c];
    float4 o;
    o.x = w0 * a.x + w1 * b.x;
    o.y = w0 * a.y + w1 * b.y;
    o.z = w0 * a.z + w1 * b.z;
    o.w = w0 * a.w + w1 * b.w;
    ((float4*)(out + (size_t)t * DM))[c] = o;
}

// ===========================================================================
// Launch
// ===========================================================================
extern "C" void kernel_launch(void* const* d_in, const int* in_sizes, int n_in,
                              void* d_out, int out_size) {
    const float* x  = (const float*)d_in[0];
    const float* Wg = (const float*)d_in[1];
    const float* bg = (const float*)d_in[2];
    const float* W1 = (const float*)d_in[3];
    const float* b1 = (const float*)d_in[4];
    const float* W2 = (const float*)d_in[5];
    const float* b2 = (const float*)d_in[6];

    float* out_y = (float*)d_out;
    int write_logits = (out_size >= TT * (DM + NE)) ? 1 : 0;
    float* logits = out_y + (size_t)TT * DM;

    cudaFuncSetAttribute(moe_gemm1, cudaFuncAttributeMaxDynamicSharedMemorySize, SMEM_BYTES);
    cudaFuncSetAttribute(moe_gemm2, cudaFuncAttributeMaxDynamicSharedMemorySize, SMEM_BYTES);

    __half *w1p, *w2p;
    cudaGetSymbolAddress((void**)&w1p, g_w1);
    cudaGetSymbolAddress((void**)&w2p, g_w2);

    zero_cnt_kernel<<<1, 32>>>();
    convert_kernel<<<8192, 256>>>(W1, w1p, (size_t)NE * DM * DH / 4);
    convert_kernel<<<8192, 256>>>(W2, w2p, (size_t)NE * DH * DM / 4);
    gate_kernel<<<TT / 8, 256>>>(x, Wg, bg, logits, write_logits);
    prefix_kernel<<<1, 32>>>();

    moe_gemm1<<<dim3(DH / BN, TT / BM, NE), NTHREADS, SMEM_BYTES>>>(b1);
    moe_gemm2<<<dim3(DM / BN, TT / BM, NE), NTHREADS, SMEM_BYTES>>>(b2);

    combine_kernel<<<TT, DM / 4>>>(out_y);
}

// round 9
// speedup vs baseline: 2.7549x; 1.0991x over previous
#include <cuda_runtime.h>
#include <cuda_fp16.h>
#include <cstdint>
#include <math.h>

// Problem constants (MoELayer_76433237999752)
#define TT 4096      // tokens = B*S
#define DM 1024      // d_model
#define DH 4096      // d_hidden
#define NE 8         // experts
#define RTOT (TT*2)  // total routed rows (top-2)
#define HPAD 128     // row padding so GEMM2 A-tile reads never go OOB

// GEMM tiling: CTA tile 128x128, BK=64, 256 threads = 8 warps (2x4),
// warp tile 64x32, 3-stage cp.async, 2 CTAs/SM, single-pass fp16 mma.
#define BM 128
#define BN 128
#define BK 64
#define NTHREADS 256
// SMEM stage layout (bytes): A[128 rows x 144B] B[64 rows x 272B]
#define A_OFF 0
#define B_OFF 18432
#define STAGE_BYTES 35840
#define NSTAGE 3
#define SMEM_BYTES (STAGE_BYTES * NSTAGE)   // 107520

// ===========================================================================
// Device-global scratch
// ===========================================================================
__device__ int    g_cnt [NE];
__device__ int    g_base[NE];
__device__ int    g_tok [NE * TT];
__device__ float  g_wt  [NE * TT];                    // combine weight per slot
__device__ __half g_x  [(size_t)TT * DM];             // x in fp16
__device__ __half g_w1 [(size_t)NE * DM * DH];        // W1 in fp16
__device__ __half g_w2 [(size_t)NE * DH * DM];        // W2 in fp16
__device__ __half g_h  [(size_t)(RTOT + HPAD) * DH];  // hidden, fp16

// ===========================================================================
// PTX helpers (plain sm_80-era — nothing "a"-gated)
// ===========================================================================
__device__ __forceinline__ uint32_t smem_u32(const void* p) {
    uint32_t a;
    asm("{ .reg .u64 t; cvta.to.shared.u64 t, %1; cvt.u32.u64 %0, t; }" : "=r"(a) : "l"(p));
    return a;
}
__device__ __forceinline__ void ldsm_x4(uint32_t* r, uint32_t addr) {
    asm volatile("ldmatrix.sync.aligned.m8n8.x4.shared.b16 {%0,%1,%2,%3}, [%4];"
                 : "=r"(r[0]), "=r"(r[1]), "=r"(r[2]), "=r"(r[3]) : "r"(addr));
}
__device__ __forceinline__ void ldsm_x2t(uint32_t* r, uint32_t addr) {
    asm volatile("ldmatrix.sync.aligned.m8n8.x2.trans.shared.b16 {%0,%1}, [%2];"
                 : "=r"(r[0]), "=r"(r[1]) : "r"(addr));
}
__device__ __forceinline__ void mma16816(float* c, const uint32_t* a, const uint32_t* b) {
    asm volatile("mma.sync.aligned.m16n8k16.row.col.f32.f16.f16.f32 "
                 "{%0,%1,%2,%3}, {%4,%5,%6,%7}, {%8,%9}, {%0,%1,%2,%3};"
                 : "+f"(c[0]), "+f"(c[1]), "+f"(c[2]), "+f"(c[3])
                 : "r"(a[0]), "r"(a[1]), "r"(a[2]), "r"(a[3]), "r"(b[0]), "r"(b[1]));
}
__device__ __forceinline__ void cp16(uint32_t dst, const void* src, uint32_t sz) {
    asm volatile("cp.async.cg.shared.global [%0], [%1], 16, %2;"
                 :: "r"(dst), "l"(src), "r"(sz) : "memory");
}
#define CP_COMMIT() asm volatile("cp.async.commit_group;" ::: "memory")
#define CP_WAIT(n)  asm volatile("cp.async.wait_group %0;" :: "n"(n) : "memory")

// fp32x4 -> fp16x4
__device__ __forceinline__ uint2 pack4h(float4 v) {
    __half2 h0 = __float22half2_rn(make_float2(v.x, v.y));
    __half2 h1 = __float22half2_rn(make_float2(v.z, v.w));
    return make_uint2(*(uint32_t*)&h0, *(uint32_t*)&h1);
}

// ===========================================================================
// Weight convert: fp32 -> fp16
// ===========================================================================
__global__ void convert_kernel(const float* __restrict__ in,
                               __half* __restrict__ oh, size_t n4) {
    size_t stride = (size_t)gridDim.x * blockDim.x;
    for (size_t i = (size_t)blockIdx.x * blockDim.x + threadIdx.x; i < n4; i += stride) {
        ((uint2*)oh)[i] = pack4h(((const float4*)in)[i]);
    }
}

// init: zero expert counters + zero the output y region (scatter target)
__global__ void init_kernel(float* __restrict__ out_y) {
    int i = blockIdx.x * blockDim.x + threadIdx.x;
    if (i < NE) g_cnt[i] = 0;
    size_t stride = (size_t)gridDim.x * blockDim.x;
    for (size_t j = i; j < (size_t)TT * DM / 4; j += stride)
        ((float4*)out_y)[j] = make_float4(0.f, 0.f, 0.f, 0.f);
}

// ===========================================================================
// Routing: smem-tiled gate, fused x fp16 conversion.
// ===========================================================================
__global__ void __launch_bounds__(256)
gate_kernel(const float* __restrict__ x,
            const float* __restrict__ Wg,
            const float* __restrict__ bg,
            float* __restrict__ logits_out,
            int write_logits) {
    __shared__ float s_wgT[NE][DM];   // 32 KB, transposed gate weights

    int tid  = threadIdx.x;
    int lane = tid & 31, w = tid >> 5;

    for (int i = tid; i < DM * NE; i += 256) {
        int d = i >> 3, e = i & 7;
        s_wgT[e][d] = Wg[i];
    }
    __syncthreads();

    int t = blockIdx.x * 8 + w;
    const float* xr = x + (size_t)t * DM;

    float acc[NE];
#pragma unroll
    for (int e = 0; e < NE; e++) acc[e] = 0.0f;

#pragma unroll
    for (int i = 0; i < 8; i++) {
        int d4 = i * 32 + lane;            // float4 index within row
        float4 xv = ((const float4*)xr)[d4];
        ((uint2*)(g_x + (size_t)t * DM))[d4] = pack4h(xv);
#pragma unroll
        for (int e = 0; e < NE; e++) {
            float4 wv = ((const float4*)&s_wgT[e][0])[d4];
            acc[e] += xv.x * wv.x + xv.y * wv.y + xv.z * wv.z + xv.w * wv.w;
        }
    }
#pragma unroll
    for (int e = 0; e < NE; e++)
#pragma unroll
        for (int o = 16; o > 0; o >>= 1)
            acc[e] += __shfl_xor_sync(0xffffffffu, acc[e], o);

    if (lane == 0) {
#pragma unroll
        for (int e = 0; e < NE; e++) acc[e] += bg[e];
        if (write_logits)
#pragma unroll
            for (int e = 0; e < NE; e++)
                logits_out[(size_t)t * NE + e] = acc[e];
        int i0 = 0; float v0 = acc[0];
#pragma unroll
        for (int e = 1; e < NE; e++) if (acc[e] > v0) { v0 = acc[e]; i0 = e; }
        int i1 = -1; float v1 = -INFINITY;
#pragma unroll
        for (int e = 0; e < NE; e++) {
            if (e == i0) continue;
            if (acc[e] > v1) { v1 = acc[e]; i1 = e; }
        }
        float ew  = expf(v1 - v0);
        float inv = 1.0f / (1.0f + ew);

        int s0 = atomicAdd(&g_cnt[i0], 1);
        g_tok[i0 * TT + s0] = t;
        g_wt [i0 * TT + s0] = inv;
        int s1 = atomicAdd(&g_cnt[i1], 1);
        g_tok[i1 * TT + s1] = t;
        g_wt [i1 * TT + s1] = ew * inv;
    }
}

__global__ void prefix_kernel() {
    if (threadIdx.x == 0) {
        int s = 0;
#pragma unroll
        for (int e = 0; e < NE; e++) { g_base[e] = s; s += g_cnt[e]; }
    }
}

// ===========================================================================
// GEMM core: 128x128 CTA tile, BK=64, 8 warps (2x4), warp tile 64x32,
// 3-stage cp.async, single-pass fp16 mma.
// Per thread per chunk: 4 A chunks (rows r0+32k) + 4 B chunks (krows kr0+16k).
// ===========================================================================
struct TilePtrs {
    const __half* a[4];          // A row pointers (4 rows per thread)
    uint32_t asz[4];             // 16 or 0 (zero-fill)
    const __half* b;             // B base (krow kr0)
    int aStep, bStep;            // elems to advance per kt
    int bRowStride;              // 16 * ldb (elems between the 4 B chunks)
    uint32_t aDst, bDst;         // smem offsets within stage (chunk 0)
};

__device__ __forceinline__ void issue_tile(uint32_t sb, int stage, const TilePtrs& tp, int kt) {
    uint32_t s = sb + stage * STAGE_BYTES;
    int ao = kt * tp.aStep;
    int bo = kt * tp.bStep;
#pragma unroll
    for (int i = 0; i < 4; i++)
        cp16(s + A_OFF + tp.aDst + i * 4608, tp.a[i] + ao, tp.asz[i]);   // 32 rows * 144B
#pragma unroll
    for (int i = 0; i < 4; i++)
        cp16(s + B_OFF + tp.bDst + i * 4352, tp.b + bo + i * tp.bRowStride, 16); // 16 rows * 272B
    CP_COMMIT();
}

template <int NC>
__device__ __forceinline__ void gemm_core(uint32_t sb, const TilePtrs& tp,
                                          float cacc[4][4][4],
                                          uint32_t aOff, uint32_t bOff) {
    issue_tile(sb, 0, tp, 0);
    issue_tile(sb, 1, tp, 1);
#pragma unroll 1
    for (int kt = 0; kt < NC; kt++) {
        if (kt + 1 < NC) { CP_WAIT(1); } else { CP_WAIT(0); }
        __syncthreads();
        if (kt + 2 < NC) issue_tile(sb, (kt + 2) % NSTAGE, tp, kt + 2);
        uint32_t s = sb + (kt % NSTAGE) * STAGE_BYTES;
#pragma unroll
        for (int k16 = 0; k16 < 4; k16++) {
            uint32_t ah[4][4];
#pragma unroll
            for (int mi = 0; mi < 4; mi++)
                ldsm_x4(ah[mi], s + A_OFF + aOff + mi * 2304 + k16 * 32);   // 16 rows*144B
#pragma unroll
            for (int ni = 0; ni < 4; ni++) {
                uint32_t bb[2];
                ldsm_x2t(bb, s + B_OFF + bOff + ni * 16 + k16 * 4352);       // 16 krows*272B
#pragma unroll
                for (int mi = 0; mi < 4; mi++) mma16816(cacc[mi][ni], ah[mi], bb);
            }
        }
    }
}

// warp layout: 8 warps as (wm, wn) = (wid>>2, wid&3); warp tile 64x32.
// A plane rows are 144B; B plane rows are 272B.
__device__ __forceinline__ uint32_t calc_aoff(int wm, int lane) {
    return (uint32_t)(wm * 64 + (lane & 7) + ((lane >> 3) & 1) * 8) * 144
         + (lane >> 4) * 16;
}
__device__ __forceinline__ uint32_t calc_boff(int wn, int lane) {
    return (uint32_t)(lane & 15) * 272 + wn * 64;
}

// ===========================================================================
// GEMM1: h[base+r] = relu( x[tok[r]] @ W1[e] + b1[e] )  (h stored fp16)
// ===========================================================================
__global__ void __launch_bounds__(NTHREADS, 2)
moe_gemm1(const float* __restrict__ b1) {
    int e   = blockIdx.z;
    int cnt = g_cnt[e];
    int rb  = blockIdx.y * BM;
    if (rb >= cnt) return;
    int nb   = blockIdx.x * BN;
    int base = g_base[e];

    extern __shared__ __align__(128) char smem[];
    uint32_t sb = smem_u32(smem);

    int tid  = threadIdx.x;
    int lane = tid & 31, wid = tid >> 5;
    int wm = wid >> 2, wn = wid & 3;

    TilePtrs tp;
    {
        // A: 1024 16B chunks (128 rows x 8 segs), 4 per thread: rows r0+32i
        int r0 = tid >> 3, sg = tid & 7;
#pragma unroll
        for (int i = 0; i < 4; i++) {
            int r = r0 + 32 * i;
            bool v = (rb + r) < cnt;
            int tok = g_tok[e * TT + (v ? rb + r : 0)];
            tp.a[i]  = g_x + (size_t)tok * DM + sg * 8;
            tp.asz[i] = v ? 16 : 0;
        }
        tp.aDst = (uint32_t)r0 * 144 + sg * 16;
        tp.aStep = BK;
        // B: 1024 chunks (64 k-rows x 16 segs), 4 per thread: krows kr0+16i
        int kr0 = tid >> 4, bs = tid & 15;
        size_t wbase = (size_t)e * DM * DH;
        tp.b = g_w1 + wbase + (size_t)kr0 * DH + nb + bs * 8;
        tp.bDst = (uint32_t)kr0 * 272 + bs * 16;
        tp.bStep = BK * DH;
        tp.bRowStride = 16 * DH;
    }

    uint32_t aOff = calc_aoff(wm, lane);
    uint32_t bOff = calc_boff(wn, lane);

    float cacc[4][4][4];
#pragma unroll
    for (int mi = 0; mi < 4; mi++)
#pragma unroll
        for (int ni = 0; ni < 4; ni++)
#pragma unroll
            for (int q = 0; q < 4; q++) cacc[mi][ni][q] = 0.0f;

    gemm_core<DM / BK>(sb, tp, cacc, aOff, bOff);

    const float* bb = b1 + (size_t)e * DH + nb;
    int er = wm * 64 + (lane >> 2);
    int ec = wn * 32 + (lane & 3) * 2;
#pragma unroll
    for (int mi = 0; mi < 4; mi++) {
#pragma unroll
        for (int rr = 0; rr < 2; rr++) {
            int m = er + mi * 16 + rr * 8;
            if (rb + m >= cnt) continue;
            size_t rowoff = (size_t)(base + rb + m) * DH + nb;
#pragma unroll
            for (int ni = 0; ni < 4; ni++) {
                int c = ec + ni * 8;
                float v0 = cacc[mi][ni][rr * 2 + 0] + bb[c];
                float v1 = cacc[mi][ni][rr * 2 + 1] + bb[c + 1];
                v0 = v0 > 0.f ? v0 : 0.f;
                v1 = v1 > 0.f ? v1 : 0.f;
                __half2 hv = __float22half2_rn(make_float2(v0, v1));
                *(uint32_t*)(g_h + rowoff + c) = *(uint32_t*)&hv;
            }
        }
    }
}

// ===========================================================================
// GEMM2: out[tok[r]] += w[r] * ( h[base+r] @ W2[e] + b2[e] )   (atomic scatter)
// ===========================================================================
__global__ void __launch_bounds__(NTHREADS, 2)
moe_gemm2(const float* __restrict__ b2, float* __restrict__ out) {
    int e   = blockIdx.z;
    int cnt = g_cnt[e];
    int rb  = blockIdx.y * BM;
    if (rb >= cnt) return;
    int nb   = blockIdx.x * BN;
    int base = g_base[e];

    extern __shared__ __align__(128) char smem[];
    uint32_t sb = smem_u32(smem);

    int tid  = threadIdx.x;
    int lane = tid & 31, wid = tid >> 5;
    int wm = wid >> 2, wn = wid & 3;

    TilePtrs tp;
    {
        int r0 = tid >> 3, sg = tid & 7;
#pragma unroll
        for (int i = 0; i < 4; i++) {
            int r = r0 + 32 * i;
            tp.a[i]  = g_h + (size_t)(base + rb + r) * DH + sg * 8;  // HPAD covers tails
            tp.asz[i] = 16;
        }
        tp.aDst = (uint32_t)r0 * 144 + sg * 16;
        tp.aStep = BK;
        int kr0 = tid >> 4, bs = tid & 15;
        size_t wbase = (size_t)e * DH * DM;
        tp.b = g_w2 + wbase + (size_t)kr0 * DM + nb + bs * 8;
        tp.bDst = (uint32_t)kr0 * 272 + bs * 16;
        tp.bStep = BK * DM;
        tp.bRowStride = 16 * DM;
    }

    uint32_t aOff = calc_aoff(wm, lane);
    uint32_t bOff = calc_boff(wn, lane);

    float cacc[4][4][4];
#pragma unroll
    for (int mi = 0; mi < 4; mi++)
#pragma unroll
        for (int ni = 0; ni < 4; ni++)
#pragma unroll
            for (int q = 0; q < 4; q++) cacc[mi][ni][q] = 0.0f;

    gemm_core<DH / BK>(sb, tp, cacc, aOff, bOff);

    const float* bb = b2 + (size_t)e * DM + nb;
    int er = wm * 64 + (lane >> 2);
    int ec = wn * 32 + (lane & 3) * 2;
#pragma unroll
    for (int mi = 0; mi < 4; mi++) {
#pragma unroll
        for (int rr = 0; rr < 2; rr++) {
            int m = er + mi * 16 + rr * 8;
            if (rb + m >= cnt) continue;
            int   tok = g_tok[e * TT + rb + m];
            float w   = g_wt [e * TT + rb + m];
            float* orow = out + (size_t)tok * DM + nb;
#pragma unroll
            for (int ni = 0; ni < 4; ni++) {
                int c = ec + ni * 8;
                atomicAdd(&orow[c],     w * (cacc[mi][ni][rr * 2 + 0] + bb[c]));
                atomicAdd(&orow[c + 1], w * (cacc[mi][ni][rr * 2 + 1] + bb[c + 1]));
            }
        }
    }
}

// ===========================================================================
// Launch
// ===========================================================================
extern "C" void kernel_launch(void* const* d_in, const int* in_sizes, int n_in,
                              void* d_out, int out_size) {
    const float* x  = (const float*)d_in[0];
    const float* Wg = (const float*)d_in[1];
    const float* bg = (const float*)d_in[2];
    const float* W1 = (const float*)d_in[3];
    const float* b1 = (const float*)d_in[4];
    const float* W2 = (const float*)d_in[5];
    const float* b2 = (const float*)d_in[6];

    float* out_y = (float*)d_out;
    int write_logits = (out_size >= TT * (DM + NE)) ? 1 : 0;
    float* logits = out_y + (size_t)TT * DM;

    cudaFuncSetAttribute(moe_gemm1, cudaFuncAttributeMaxDynamicSharedMemorySize, SMEM_BYTES);
    cudaFuncSetAttribute(moe_gemm2, cudaFuncAttributeMaxDynamicSharedMemorySize, SMEM_BYTES);

    __half *w1p, *w2p;
    cudaGetSymbolAddress((void**)&w1p, g_w1);
    cudaGetSymbolAddress((void**)&w2p, g_w2);

    init_kernel<<<512, 256>>>(out_y);
    convert_kernel<<<8192, 256>>>(W1, w1p, (size_t)NE * DM * DH / 4);
    convert_kernel<<<8192, 256>>>(W2, w2p, (size_t)NE * DH * DM / 4);
    gate_kernel<<<TT / 8, 256>>>(x, Wg, bg, logits, write_logits);
    prefix_kernel<<<1, 32>>>();

    moe_gemm1<<<dim3(DH / BN, TT / BM, NE), NTHREADS, SMEM_BYTES>>>(b1);
    moe_gemm2<<<dim3(DM / BN, TT / BM, NE), NTHREADS, SMEM_BYTES>>>(b2, out_y);
}

// round 10
// speedup vs baseline: 2.8134x; 1.0213x over previous
#include <cuda_runtime.h>
#include <cuda_fp16.h>
#include <cstdint>
#include <math.h>

// Problem constants (MoELayer_76433237999752)
#define TT 4096      // tokens = B*S
#define DM 1024      // d_model
#define DH 4096      // d_hidden
#define NE 8         // experts
#define RTOT (TT*2)  // total routed rows (top-2)
#define HPAD 128     // row padding so GEMM2 A-tile reads never go OOB

// GEMM tiling: CTA tile 128x128, BK=64, 256 threads = 8 warps (2x4),
// warp tile 64x32, 3-stage cp.async, 2 CTAs/SM, single-pass fp16 mma.
#define BM 128
#define BN 128
#define BK 64
#define NTHREADS 256
// SMEM stage layout (bytes): A[128 rows x 144B] B[64 rows x 272B]
#define A_OFF 0
#define B_OFF 18432
#define STAGE_BYTES 35840
#define NSTAGE 3
#define SMEM_BYTES (STAGE_BYTES * NSTAGE)   // 107520

// ===========================================================================
// Device-global scratch
// ===========================================================================
__device__ int    g_cnt [NE];
__device__ int    g_tok [NE * TT];
__device__ float  g_wt  [NE * TT];                    // combine weight per slot
__device__ __half g_x  [(size_t)TT * DM];             // x in fp16
__device__ __half g_w1 [(size_t)NE * DM * DH];        // W1 in fp16
__device__ __half g_w2 [(size_t)NE * DH * DM];        // W2 in fp16
__device__ __half g_h  [(size_t)(RTOT + HPAD) * DH];  // hidden, fp16

// ===========================================================================
// PTX helpers (plain sm_80-era — nothing "a"-gated)
// ===========================================================================
__device__ __forceinline__ uint32_t smem_u32(const void* p) {
    uint32_t a;
    asm("{ .reg .u64 t; cvta.to.shared.u64 t, %1; cvt.u32.u64 %0, t; }" : "=r"(a) : "l"(p));
    return a;
}
__device__ __forceinline__ void ldsm_x4(uint32_t* r, uint32_t addr) {
    asm volatile("ldmatrix.sync.aligned.m8n8.x4.shared.b16 {%0,%1,%2,%3}, [%4];"
                 : "=r"(r[0]), "=r"(r[1]), "=r"(r[2]), "=r"(r[3]) : "r"(addr));
}
__device__ __forceinline__ void ldsm_x2t(uint32_t* r, uint32_t addr) {
    asm volatile("ldmatrix.sync.aligned.m8n8.x2.trans.shared.b16 {%0,%1}, [%2];"
                 : "=r"(r[0]), "=r"(r[1]) : "r"(addr));
}
__device__ __forceinline__ void mma16816(float* c, const uint32_t* a, const uint32_t* b) {
    asm volatile("mma.sync.aligned.m16n8k16.row.col.f32.f16.f16.f32 "
                 "{%0,%1,%2,%3}, {%4,%5,%6,%7}, {%8,%9}, {%0,%1,%2,%3};"
                 : "+f"(c[0]), "+f"(c[1]), "+f"(c[2]), "+f"(c[3])
                 : "r"(a[0]), "r"(a[1]), "r"(a[2]), "r"(a[3]), "r"(b[0]), "r"(b[1]));
}
__device__ __forceinline__ void cp16(uint32_t dst, const void* src, uint32_t sz) {
    asm volatile("cp.async.cg.shared.global [%0], [%1], 16, %2;"
                 :: "r"(dst), "l"(src), "r"(sz) : "memory");
}
#define CP_COMMIT() asm volatile("cp.async.commit_group;" ::: "memory")
#define CP_WAIT(n)  asm volatile("cp.async.wait_group %0;" :: "n"(n) : "memory")

// fp32x4 -> fp16x4
__device__ __forceinline__ uint2 pack4h(float4 v) {
    __half2 h0 = __float22half2_rn(make_float2(v.x, v.y));
    __half2 h1 = __float22half2_rn(make_float2(v.z, v.w));
    return make_uint2(*(uint32_t*)&h0, *(uint32_t*)&h1);
}

// ===========================================================================
// Fused prep kernel: 1536 blocks x 256 threads.
//   blocks [0,512):    gate (8 tokens/block) + fused x fp16 conversion
//   blocks [512,1024): convert W1 fp32->fp16
//   blocks [1024,1536): convert W2 fp32->fp16
// g_cnt must be zeroed beforehand (memset node).
// ===========================================================================
#define GATE_BLKS 512
#define CONV_BLKS 512
#define CONV_N4   ((size_t)NE * DM * DH / 4)   // 8388608 float4 per weight

__global__ void __launch_bounds__(256)
prep_kernel(const float* __restrict__ x,
            const float* __restrict__ Wg,
            const float* __restrict__ bg,
            const float* __restrict__ W1,
            const float* __restrict__ W2,
            __half* __restrict__ w1o,
            __half* __restrict__ w2o,
            float* __restrict__ logits_out,
            int write_logits) {
    int bx  = blockIdx.x;
    int tid = threadIdx.x;

    if (bx >= GATE_BLKS) {
        // ---- weight conversion ----
        const float* src;
        __half* dst;
        int cb;
        if (bx < GATE_BLKS + CONV_BLKS) { src = W1; dst = w1o; cb = bx - GATE_BLKS; }
        else                            { src = W2; dst = w2o; cb = bx - GATE_BLKS - CONV_BLKS; }
        size_t stride = (size_t)CONV_BLKS * 256;
        for (size_t i = (size_t)cb * 256 + tid; i < CONV_N4; i += stride)
            ((uint2*)dst)[i] = pack4h(((const float4*)src)[i]);
        return;
    }

    // ---- gate ----
    __shared__ float s_wgT[NE][DM];   // 32 KB, transposed gate weights
    int lane = tid & 31, w = tid >> 5;

    for (int i = tid; i < DM * NE; i += 256) {
        int d = i >> 3, e = i & 7;
        s_wgT[e][d] = Wg[i];
    }
    __syncthreads();

    int t = bx * 8 + w;
    const float* xr = x + (size_t)t * DM;

    float acc[NE];
#pragma unroll
    for (int e = 0; e < NE; e++) acc[e] = 0.0f;

#pragma unroll
    for (int i = 0; i < 8; i++) {
        int d4 = i * 32 + lane;            // float4 index within row
        float4 xv = ((const float4*)xr)[d4];
        ((uint2*)(g_x + (size_t)t * DM))[d4] = pack4h(xv);
#pragma unroll
        for (int e = 0; e < NE; e++) {
            float4 wv = ((const float4*)&s_wgT[e][0])[d4];
            acc[e] += xv.x * wv.x + xv.y * wv.y + xv.z * wv.z + xv.w * wv.w;
        }
    }
#pragma unroll
    for (int e = 0; e < NE; e++)
#pragma unroll
        for (int o = 16; o > 0; o >>= 1)
            acc[e] += __shfl_xor_sync(0xffffffffu, acc[e], o);

    if (lane == 0) {
#pragma unroll
        for (int e = 0; e < NE; e++) acc[e] += bg[e];
        if (write_logits)
#pragma unroll
            for (int e = 0; e < NE; e++)
                logits_out[(size_t)t * NE + e] = acc[e];
        int i0 = 0; float v0 = acc[0];
#pragma unroll
        for (int e = 1; e < NE; e++) if (acc[e] > v0) { v0 = acc[e]; i0 = e; }
        int i1 = -1; float v1 = -INFINITY;
#pragma unroll
        for (int e = 0; e < NE; e++) {
            if (e == i0) continue;
            if (acc[e] > v1) { v1 = acc[e]; i1 = e; }
        }
        float ew  = expf(v1 - v0);
        float inv = 1.0f / (1.0f + ew);

        int s0 = atomicAdd(&g_cnt[i0], 1);
        g_tok[i0 * TT + s0] = t;
        g_wt [i0 * TT + s0] = inv;
        int s1 = atomicAdd(&g_cnt[i1], 1);
        g_tok[i1 * TT + s1] = t;
        g_wt [i1 * TT + s1] = ew * inv;
    }
}

// ===========================================================================
// GEMM core: 128x128 CTA tile, BK=64, 8 warps (2x4), warp tile 64x32,
// 3-stage cp.async, single-pass fp16 mma.
// Per thread per chunk: 4 A chunks (rows r0+32k) + 4 B chunks (krows kr0+16k).
// ===========================================================================
struct TilePtrs {
    const __half* a[4];          // A row pointers (4 rows per thread)
    uint32_t asz[4];             // 16 or 0 (zero-fill)
    const __half* b;             // B base (krow kr0)
    int aStep, bStep;            // elems to advance per kt
    int bRowStride;              // 16 * ldb (elems between the 4 B chunks)
    uint32_t aDst, bDst;         // smem offsets within stage (chunk 0)
};

__device__ __forceinline__ void issue_tile(uint32_t sb, int stage, const TilePtrs& tp, int kt) {
    uint32_t s = sb + stage * STAGE_BYTES;
    int ao = kt * tp.aStep;
    int bo = kt * tp.bStep;
#pragma unroll
    for (int i = 0; i < 4; i++)
        cp16(s + A_OFF + tp.aDst + i * 4608, tp.a[i] + ao, tp.asz[i]);   // 32 rows * 144B
#pragma unroll
    for (int i = 0; i < 4; i++)
        cp16(s + B_OFF + tp.bDst + i * 4352, tp.b + bo + i * tp.bRowStride, 16); // 16 rows * 272B
    CP_COMMIT();
}

template <int NC>
__device__ __forceinline__ void gemm_core(uint32_t sb, const TilePtrs& tp,
                                          float cacc[4][4][4],
                                          uint32_t aOff, uint32_t bOff) {
    issue_tile(sb, 0, tp, 0);
    issue_tile(sb, 1, tp, 1);
#pragma unroll 1
    for (int kt = 0; kt < NC; kt++) {
        if (kt + 1 < NC) { CP_WAIT(1); } else { CP_WAIT(0); }
        __syncthreads();
        if (kt + 2 < NC) issue_tile(sb, (kt + 2) % NSTAGE, tp, kt + 2);
        uint32_t s = sb + (kt % NSTAGE) * STAGE_BYTES;
#pragma unroll
        for (int k16 = 0; k16 < 4; k16++) {
            uint32_t ah[4][4];
#pragma unroll
            for (int mi = 0; mi < 4; mi++)
                ldsm_x4(ah[mi], s + A_OFF + aOff + mi * 2304 + k16 * 32);   // 16 rows*144B
#pragma unroll
            for (int ni = 0; ni < 4; ni++) {
                uint32_t bb[2];
                ldsm_x2t(bb, s + B_OFF + bOff + ni * 16 + k16 * 4352);       // 16 krows*272B
#pragma unroll
                for (int mi = 0; mi < 4; mi++) mma16816(cacc[mi][ni], ah[mi], bb);
            }
        }
    }
}

// warp layout: 8 warps as (wm, wn) = (wid>>2, wid&3); warp tile 64x32.
// A plane rows are 144B; B plane rows are 272B.
__device__ __forceinline__ uint32_t calc_aoff(int wm, int lane) {
    return (uint32_t)(wm * 64 + (lane & 7) + ((lane >> 3) & 1) * 8) * 144
         + (lane >> 4) * 16;
}
__device__ __forceinline__ uint32_t calc_boff(int wn, int lane) {
    return (uint32_t)(lane & 15) * 272 + wn * 64;
}

// inline exclusive prefix over g_cnt
__device__ __forceinline__ int calc_base(int e) {
    int base = 0;
#pragma unroll
    for (int i = 0; i < NE; i++)
        if (i < e) base += g_cnt[i];
    return base;
}

// ===========================================================================
// GEMM1: h[base+r] = relu( x[tok[r]] @ W1[e] + b1[e] )  (h stored fp16)
// ===========================================================================
__global__ void __launch_bounds__(NTHREADS, 2)
moe_gemm1(const float* __restrict__ b1) {
    int e   = blockIdx.z;
    int cnt = g_cnt[e];
    int rb  = blockIdx.y * BM;
    if (rb >= cnt) return;
    int nb   = blockIdx.x * BN;
    int base = calc_base(e);

    extern __shared__ __align__(128) char smem[];
    uint32_t sb = smem_u32(smem);

    int tid  = threadIdx.x;
    int lane = tid & 31, wid = tid >> 5;
    int wm = wid >> 2, wn = wid & 3;

    TilePtrs tp;
    {
        // A: 1024 16B chunks (128 rows x 8 segs), 4 per thread: rows r0+32i
        int r0 = tid >> 3, sg = tid & 7;
#pragma unroll
        for (int i = 0; i < 4; i++) {
            int r = r0 + 32 * i;
            bool v = (rb + r) < cnt;
            int tok = g_tok[e * TT + (v ? rb + r : 0)];
            tp.a[i]  = g_x + (size_t)tok * DM + sg * 8;
            tp.asz[i] = v ? 16 : 0;
        }
        tp.aDst = (uint32_t)r0 * 144 + sg * 16;
        tp.aStep = BK;
        // B: 1024 chunks (64 k-rows x 16 segs), 4 per thread: krows kr0+16i
        int kr0 = tid >> 4, bs = tid & 15;
        size_t wbase = (size_t)e * DM * DH;
        tp.b = g_w1 + wbase + (size_t)kr0 * DH + nb + bs * 8;
        tp.bDst = (uint32_t)kr0 * 272 + bs * 16;
        tp.bStep = BK * DH;
        tp.bRowStride = 16 * DH;
    }

    uint32_t aOff = calc_aoff(wm, lane);
    uint32_t bOff = calc_boff(wn, lane);

    float cacc[4][4][4];
#pragma unroll
    for (int mi = 0; mi < 4; mi++)
#pragma unroll
        for (int ni = 0; ni < 4; ni++)
#pragma unroll
            for (int q = 0; q < 4; q++) cacc[mi][ni][q] = 0.0f;

    gemm_core<DM / BK>(sb, tp, cacc, aOff, bOff);

    const float* bb = b1 + (size_t)e * DH + nb;
    int er = wm * 64 + (lane >> 2);
    int ec = wn * 32 + (lane & 3) * 2;
#pragma unroll
    for (int mi = 0; mi < 4; mi++) {
#pragma unroll
        for (int rr = 0; rr < 2; rr++) {
            int m = er + mi * 16 + rr * 8;
            if (rb + m >= cnt) continue;
            size_t rowoff = (size_t)(base + rb + m) * DH + nb;
#pragma unroll
            for (int ni = 0; ni < 4; ni++) {
                int c = ec + ni * 8;
                float v0 = cacc[mi][ni][rr * 2 + 0] + bb[c];
                float v1 = cacc[mi][ni][rr * 2 + 1] + bb[c + 1];
                v0 = v0 > 0.f ? v0 : 0.f;
                v1 = v1 > 0.f ? v1 : 0.f;
                __half2 hv = __float22half2_rn(make_float2(v0, v1));
                *(uint32_t*)(g_h + rowoff + c) = *(uint32_t*)&hv;
            }
        }
    }
}

// ===========================================================================
// GEMM2: out[tok[r]] += w[r] * ( h[base+r] @ W2[e] + b2[e] )   (atomic scatter)
// ===========================================================================
__global__ void __launch_bounds__(NTHREADS, 2)
moe_gemm2(const float* __restrict__ b2, float* __restrict__ out) {
    int e   = blockIdx.z;
    int cnt = g_cnt[e];
    int rb  = blockIdx.y * BM;
    if (rb >= cnt) return;
    int nb   = blockIdx.x * BN;
    int base = calc_base(e);

    extern __shared__ __align__(128) char smem[];
    uint32_t sb = smem_u32(smem);

    int tid  = threadIdx.x;
    int lane = tid & 31, wid = tid >> 5;
    int wm = wid >> 2, wn = wid & 3;

    TilePtrs tp;
    {
        int r0 = tid >> 3, sg = tid & 7;
#pragma unroll
        for (int i = 0; i < 4; i++) {
            int r = r0 + 32 * i;
            tp.a[i]  = g_h + (size_t)(base + rb + r) * DH + sg * 8;  // HPAD covers tails
            tp.asz[i] = 16;
        }
        tp.aDst = (uint32_t)r0 * 144 + sg * 16;
        tp.aStep = BK;
        int kr0 = tid >> 4, bs = tid & 15;
        size_t wbase = (size_t)e * DH * DM;
        tp.b = g_w2 + wbase + (size_t)kr0 * DM + nb + bs * 8;
        tp.bDst = (uint32_t)kr0 * 272 + bs * 16;
        tp.bStep = BK * DM;
        tp.bRowStride = 16 * DM;
    }

    uint32_t aOff = calc_aoff(wm, lane);
    uint32_t bOff = calc_boff(wn, lane);

    float cacc[4][4][4];
#pragma unroll
    for (int mi = 0; mi < 4; mi++)
#pragma unroll
        for (int ni = 0; ni < 4; ni++)
#pragma unroll
            for (int q = 0; q < 4; q++) cacc[mi][ni][q] = 0.0f;

    gemm_core<DH / BK>(sb, tp, cacc, aOff, bOff);

    const float* bb = b2 + (size_t)e * DM + nb;
    int er = wm * 64 + (lane >> 2);
    int ec = wn * 32 + (lane & 3) * 2;
#pragma unroll
    for (int mi = 0; mi < 4; mi++) {
#pragma unroll
        for (int rr = 0; rr < 2; rr++) {
            int m = er + mi * 16 + rr * 8;
            if (rb + m >= cnt) continue;
            int   tok = g_tok[e * TT + rb + m];
            float w   = g_wt [e * TT + rb + m];
            float* orow = out + (size_t)tok * DM + nb;
#pragma unroll
            for (int ni = 0; ni < 4; ni++) {
                int c = ec + ni * 8;
                atomicAdd(&orow[c],     w * (cacc[mi][ni][rr * 2 + 0] + bb[c]));
                atomicAdd(&orow[c + 1], w * (cacc[mi][ni][rr * 2 + 1] + bb[c + 1]));
            }
        }
    }
}

// ===========================================================================
// Launch
// ===========================================================================
extern "C" void kernel_launch(void* const* d_in, const int* in_sizes, int n_in,
                              void* d_out, int out_size) {
    const float* x  = (const float*)d_in[0];
    const float* Wg = (const float*)d_in[1];
    const float* bg = (const float*)d_in[2];
    const float* W1 = (const float*)d_in[3];
    const float* b1 = (const float*)d_in[4];
    const float* W2 = (const float*)d_in[5];
    const float* b2 = (const float*)d_in[6];

    float* out_y = (float*)d_out;
    int write_logits = (out_size >= TT * (DM + NE)) ? 1 : 0;
    float* logits = out_y + (size_t)TT * DM;

    cudaFuncSetAttribute(moe_gemm1, cudaFuncAttributeMaxDynamicSharedMemorySize, SMEM_BYTES);
    cudaFuncSetAttribute(moe_gemm2, cudaFuncAttributeMaxDynamicSharedMemorySize, SMEM_BYTES);

    __half *w1p, *w2p;
    cudaGetSymbolAddress((void**)&w1p, g_w1);
    cudaGetSymbolAddress((void**)&w2p, g_w2);
    int* cntp;
    cudaGetSymbolAddress((void**)&cntp, g_cnt);

    cudaMemsetAsync(cntp, 0, NE * sizeof(int));
    cudaMemsetAsync(out_y, 0, (size_t)TT * DM * sizeof(float));

    prep_kernel<<<GATE_BLKS + 2 * CONV_BLKS, 256>>>(x, Wg, bg, W1, W2,
                                                    w1p, w2p, logits, write_logits);

    moe_gemm1<<<dim3(DH / BN, TT / BM, NE), NTHREADS, SMEM_BYTES>>>(b1);
    moe_gemm2<<<dim3(DM / BN, TT / BM, NE), NTHREADS, SMEM_BYTES>>>(b2, out_y);
}

// round 11
// speedup vs baseline: 2.8772x; 1.0227x over previous
#include <cuda_runtime.h>
#include <cuda_fp16.h>
#include <cstdint>
#include <math.h>

// Problem constants (MoELayer_76433237999752)
#define TT 4096      // tokens = B*S
#define DM 1024      // d_model
#define DH 4096      // d_hidden
#define NE 8         // experts
#define RTOT (TT*2)  // total routed rows (top-2)
#define HPAD 128     // row padding so GEMM2 A-tile reads never go OOB

// GEMM tiling: CTA tile 128x128, BK=64, 256 threads = 8 warps (2x4),
// warp tile 64x32, 3-stage cp.async, 2 CTAs/SM, single-pass fp16 mma.
#define BM 128
#define BN 128
#define BK 64
#define NTHREADS 256
// SMEM stage layout (bytes): A[128 rows x 144B] B[64 rows x 272B]
#define A_OFF 0
#define B_OFF 18432
#define STAGE_BYTES 35840
#define NSTAGE 3
#define SMEM_BYTES (STAGE_BYTES * NSTAGE)   // 107520

// ===========================================================================
// Device-global scratch
// ===========================================================================
__device__ int    g_cnt [NE];
__device__ int    g_tok [NE * TT];
__device__ float  g_wt  [NE * TT];                    // combine weight per slot
__device__ __half g_x  [(size_t)TT * DM];             // x in fp16
__device__ __half g_w1 [(size_t)NE * DM * DH];        // W1 in fp16
__device__ __half g_w2 [(size_t)NE * DH * DM];        // W2 in fp16
__device__ __half g_h  [(size_t)(RTOT + HPAD) * DH];  // hidden, fp16

// ===========================================================================
// PTX helpers (plain sm_80-era — nothing "a"-gated)
// ===========================================================================
__device__ __forceinline__ uint32_t smem_u32(const void* p) {
    uint32_t a;
    asm("{ .reg .u64 t; cvta.to.shared.u64 t, %1; cvt.u32.u64 %0, t; }" : "=r"(a) : "l"(p));
    return a;
}
__device__ __forceinline__ void ldsm_x4(uint32_t* r, uint32_t addr) {
    asm volatile("ldmatrix.sync.aligned.m8n8.x4.shared.b16 {%0,%1,%2,%3}, [%4];"
                 : "=r"(r[0]), "=r"(r[1]), "=r"(r[2]), "=r"(r[3]) : "r"(addr));
}
__device__ __forceinline__ void ldsm_x2t(uint32_t* r, uint32_t addr) {
    asm volatile("ldmatrix.sync.aligned.m8n8.x2.trans.shared.b16 {%0,%1}, [%2];"
                 : "=r"(r[0]), "=r"(r[1]) : "r"(addr));
}
__device__ __forceinline__ void mma16816(float* c, const uint32_t* a, const uint32_t* b) {
    asm volatile("mma.sync.aligned.m16n8k16.row.col.f32.f16.f16.f32 "
                 "{%0,%1,%2,%3}, {%4,%5,%6,%7}, {%8,%9}, {%0,%1,%2,%3};"
                 : "+f"(c[0]), "+f"(c[1]), "+f"(c[2]), "+f"(c[3])
                 : "r"(a[0]), "r"(a[1]), "r"(a[2]), "r"(a[3]), "r"(b[0]), "r"(b[1]));
}
__device__ __forceinline__ void cp16(uint32_t dst, const void* src, uint32_t sz) {
    asm volatile("cp.async.cg.shared.global [%0], [%1], 16, %2;"
                 :: "r"(dst), "l"(src), "r"(sz) : "memory");
}
#define CP_COMMIT() asm volatile("cp.async.commit_group;" ::: "memory")
#define CP_WAIT(n)  asm volatile("cp.async.wait_group %0;" :: "n"(n) : "memory")

// fp32x4 -> fp16x4
__device__ __forceinline__ uint2 pack4h(float4 v) {
    __half2 h0 = __float22half2_rn(make_float2(v.x, v.y));
    __half2 h1 = __float22half2_rn(make_float2(v.z, v.w));
    return make_uint2(*(uint32_t*)&h0, *(uint32_t*)&h1);
}

// ===========================================================================
// Fused prep kernel: 1024 blocks x 256 threads.
//   blocks [0,512):    gate (8 tokens/block) + fused x fp16 conversion
//   blocks [512,1024): convert W1 fp32->fp16
// g_cnt must be zeroed beforehand (memset node). W2 is converted inside gemm1.
// ===========================================================================
#define GATE_BLKS 512
#define CONV_BLKS 512
#define CONV_N4   ((size_t)NE * DM * DH / 4)   // 8388608 float4 per weight

__global__ void __launch_bounds__(256)
prep_kernel(const float* __restrict__ x,
            const float* __restrict__ Wg,
            const float* __restrict__ bg,
            const float* __restrict__ W1,
            __half* __restrict__ w1o,
            float* __restrict__ logits_out,
            int write_logits) {
    int bx  = blockIdx.x;
    int tid = threadIdx.x;

    if (bx >= GATE_BLKS) {
        // ---- W1 conversion ----
        int cb = bx - GATE_BLKS;
        size_t stride = (size_t)CONV_BLKS * 256;
        for (size_t i = (size_t)cb * 256 + tid; i < CONV_N4; i += stride)
            ((uint2*)w1o)[i] = pack4h(((const float4*)W1)[i]);
        return;
    }

    // ---- gate ----
    __shared__ float s_wgT[NE][DM];   // 32 KB, transposed gate weights
    int lane = tid & 31, w = tid >> 5;

    for (int i = tid; i < DM * NE; i += 256) {
        int d = i >> 3, e = i & 7;
        s_wgT[e][d] = Wg[i];
    }
    __syncthreads();

    int t = bx * 8 + w;
    const float* xr = x + (size_t)t * DM;

    float acc[NE];
#pragma unroll
    for (int e = 0; e < NE; e++) acc[e] = 0.0f;

#pragma unroll
    for (int i = 0; i < 8; i++) {
        int d4 = i * 32 + lane;            // float4 index within row
        float4 xv = ((const float4*)xr)[d4];
        ((uint2*)(g_x + (size_t)t * DM))[d4] = pack4h(xv);
#pragma unroll
        for (int e = 0; e < NE; e++) {
            float4 wv = ((const float4*)&s_wgT[e][0])[d4];
            acc[e] += xv.x * wv.x + xv.y * wv.y + xv.z * wv.z + xv.w * wv.w;
        }
    }
#pragma unroll
    for (int e = 0; e < NE; e++)
#pragma unroll
        for (int o = 16; o > 0; o >>= 1)
            acc[e] += __shfl_xor_sync(0xffffffffu, acc[e], o);

    if (lane == 0) {
#pragma unroll
        for (int e = 0; e < NE; e++) acc[e] += bg[e];
        if (write_logits)
#pragma unroll
            for (int e = 0; e < NE; e++)
                logits_out[(size_t)t * NE + e] = acc[e];
        int i0 = 0; float v0 = acc[0];
#pragma unroll
        for (int e = 1; e < NE; e++) if (acc[e] > v0) { v0 = acc[e]; i0 = e; }
        int i1 = -1; float v1 = -INFINITY;
#pragma unroll
        for (int e = 0; e < NE; e++) {
            if (e == i0) continue;
            if (acc[e] > v1) { v1 = acc[e]; i1 = e; }
        }
        float ew  = expf(v1 - v0);
        float inv = 1.0f / (1.0f + ew);

        int s0 = atomicAdd(&g_cnt[i0], 1);
        g_tok[i0 * TT + s0] = t;
        g_wt [i0 * TT + s0] = inv;
        int s1 = atomicAdd(&g_cnt[i1], 1);
        g_tok[i1 * TT + s1] = t;
        g_wt [i1 * TT + s1] = ew * inv;
    }
}

// ===========================================================================
// GEMM core: 128x128 CTA tile, BK=64, 8 warps (2x4), warp tile 64x32,
// 3-stage cp.async, single-pass fp16 mma.
// Per thread per chunk: 4 A chunks (rows r0+32k) + 4 B chunks (krows kr0+16k).
// ===========================================================================
struct TilePtrs {
    const __half* a[4];          // A row pointers (4 rows per thread)
    uint32_t asz[4];             // 16 or 0 (zero-fill)
    const __half* b;             // B base (krow kr0)
    int aStep, bStep;            // elems to advance per kt
    int bRowStride;              // 16 * ldb (elems between the 4 B chunks)
    uint32_t aDst, bDst;         // smem offsets within stage (chunk 0)
};

__device__ __forceinline__ void issue_tile(uint32_t sb, int stage, const TilePtrs& tp, int kt) {
    uint32_t s = sb + stage * STAGE_BYTES;
    int ao = kt * tp.aStep;
    int bo = kt * tp.bStep;
#pragma unroll
    for (int i = 0; i < 4; i++)
        cp16(s + A_OFF + tp.aDst + i * 4608, tp.a[i] + ao, tp.asz[i]);   // 32 rows * 144B
#pragma unroll
    for (int i = 0; i < 4; i++)
        cp16(s + B_OFF + tp.bDst + i * 4352, tp.b + bo + i * tp.bRowStride, 16); // 16 rows * 272B
    CP_COMMIT();
}

template <int NC>
__device__ __forceinline__ void gemm_core(uint32_t sb, const TilePtrs& tp,
                                          float cacc[4][4][4],
                                          uint32_t aOff, uint32_t bOff) {
    issue_tile(sb, 0, tp, 0);
    issue_tile(sb, 1, tp, 1);
#pragma unroll 1
    for (int kt = 0; kt < NC; kt++) {
        if (kt + 1 < NC) { CP_WAIT(1); } else { CP_WAIT(0); }
        __syncthreads();
        if (kt + 2 < NC) issue_tile(sb, (kt + 2) % NSTAGE, tp, kt + 2);
        uint32_t s = sb + (kt % NSTAGE) * STAGE_BYTES;
#pragma unroll
        for (int k16 = 0; k16 < 4; k16++) {
            uint32_t ah[4][4];
#pragma unroll
            for (int mi = 0; mi < 4; mi++)
                ldsm_x4(ah[mi], s + A_OFF + aOff + mi * 2304 + k16 * 32);   // 16 rows*144B
#pragma unroll
            for (int ni = 0; ni < 4; ni++) {
                uint32_t bb[2];
                ldsm_x2t(bb, s + B_OFF + bOff + ni * 16 + k16 * 4352);       // 16 krows*272B
#pragma unroll
                for (int mi = 0; mi < 4; mi++) mma16816(cacc[mi][ni], ah[mi], bb);
            }
        }
    }
}

// warp layout: 8 warps as (wm, wn) = (wid>>2, wid&3); warp tile 64x32.
// A plane rows are 144B; B plane rows are 272B.
__device__ __forceinline__ uint32_t calc_aoff(int wm, int lane) {
    return (uint32_t)(wm * 64 + (lane & 7) + ((lane >> 3) & 1) * 8) * 144
         + (lane >> 4) * 16;
}
__device__ __forceinline__ uint32_t calc_boff(int wn, int lane) {
    return (uint32_t)(lane & 15) * 272 + wn * 64;
}

// inline exclusive prefix over g_cnt
__device__ __forceinline__ int calc_base(int e) {
    int base = 0;
#pragma unroll
    for (int i = 0; i < NE; i++)
        if (i < e) base += g_cnt[i];
    return base;
}

// W2 convert slice: each gemm1 block (8192 total) converts 1024 float4.
__device__ __forceinline__ void convert_w2_slice(const float* __restrict__ W2,
                                                 __half* __restrict__ w2o,
                                                 int tid) {
    size_t cbid = ((size_t)blockIdx.z * gridDim.y + blockIdx.y) * gridDim.x
                + blockIdx.x;
    size_t b0 = cbid * 1024 + tid;          // 8192 blocks * 1024 = CONV_N4
#pragma unroll
    for (int i = 0; i < 4; i++)
        ((uint2*)w2o)[b0 + i * 256] = pack4h(((const float4*)W2)[b0 + i * 256]);
}

// ===========================================================================
// GEMM1: h[base+r] = relu( x[tok[r]] @ W1[e] + b1[e] )  (h stored fp16)
// Every block also converts a slice of W2 (early-exit blocks: immediately;
// working blocks: after their epilogue) — overlaps the convert with MMA.
// ===========================================================================
__global__ void __launch_bounds__(NTHREADS, 2)
moe_gemm1(const float* __restrict__ b1,
          const float* __restrict__ W2, __half* __restrict__ w2o) {
    int e   = blockIdx.z;
    int cnt = g_cnt[e];
    int rb  = blockIdx.y * BM;
    int tid = threadIdx.x;

    if (rb >= cnt) {                       // early-exit block: just convert
        convert_w2_slice(W2, w2o, tid);
        return;
    }
    int nb   = blockIdx.x * BN;
    int base = calc_base(e);

    extern __shared__ __align__(128) char smem[];
    uint32_t sb = smem_u32(smem);

    int lane = tid & 31, wid = tid >> 5;
    int wm = wid >> 2, wn = wid & 3;

    TilePtrs tp;
    {
        // A: 1024 16B chunks (128 rows x 8 segs), 4 per thread: rows r0+32i
        int r0 = tid >> 3, sg = tid & 7;
#pragma unroll
        for (int i = 0; i < 4; i++) {
            int r = r0 + 32 * i;
            bool v = (rb + r) < cnt;
            int tok = g_tok[e * TT + (v ? rb + r : 0)];
            tp.a[i]  = g_x + (size_t)tok * DM + sg * 8;
            tp.asz[i] = v ? 16 : 0;
        }
        tp.aDst = (uint32_t)r0 * 144 + sg * 16;
        tp.aStep = BK;
        // B: 1024 chunks (64 k-rows x 16 segs), 4 per thread: krows kr0+16i
        int kr0 = tid >> 4, bs = tid & 15;
        size_t wbase = (size_t)e * DM * DH;
        tp.b = g_w1 + wbase + (size_t)kr0 * DH + nb + bs * 8;
        tp.bDst = (uint32_t)kr0 * 272 + bs * 16;
        tp.bStep = BK * DH;
        tp.bRowStride = 16 * DH;
    }

    uint32_t aOff = calc_aoff(wm, lane);
    uint32_t bOff = calc_boff(wn, lane);

    float cacc[4][4][4];
#pragma unroll
    for (int mi = 0; mi < 4; mi++)
#pragma unroll
        for (int ni = 0; ni < 4; ni++)
#pragma unroll
            for (int q = 0; q < 4; q++) cacc[mi][ni][q] = 0.0f;

    gemm_core<DM / BK>(sb, tp, cacc, aOff, bOff);

    const float* bb = b1 + (size_t)e * DH + nb;
    int er = wm * 64 + (lane >> 2);
    int ec = wn * 32 + (lane & 3) * 2;
#pragma unroll
    for (int mi = 0; mi < 4; mi++) {
#pragma unroll
        for (int rr = 0; rr < 2; rr++) {
            int m = er + mi * 16 + rr * 8;
            if (rb + m >= cnt) continue;
            size_t rowoff = (size_t)(base + rb + m) * DH + nb;
#pragma unroll
            for (int ni = 0; ni < 4; ni++) {
                int c = ec + ni * 8;
                float v0 = cacc[mi][ni][rr * 2 + 0] + bb[c];
                float v1 = cacc[mi][ni][rr * 2 + 1] + bb[c + 1];
                v0 = v0 > 0.f ? v0 : 0.f;
                v1 = v1 > 0.f ? v1 : 0.f;
                __half2 hv = __float22half2_rn(make_float2(v0, v1));
                *(uint32_t*)(g_h + rowoff + c) = *(uint32_t*)&hv;
            }
        }
    }

    convert_w2_slice(W2, w2o, tid);        // working block: convert at the end
}

// ===========================================================================
// GEMM2: out[tok[r]] += w[r] * ( h[base+r] @ W2[e] + b2[e] )   (atomic scatter)
// ===========================================================================
__global__ void __launch_bounds__(NTHREADS, 2)
moe_gemm2(const float* __restrict__ b2, float* __restrict__ out) {
    int e   = blockIdx.z;
    int cnt = g_cnt[e];
    int rb  = blockIdx.y * BM;
    if (rb >= cnt) return;
    int nb   = blockIdx.x * BN;
    int base = calc_base(e);

    extern __shared__ __align__(128) char smem[];
    uint32_t sb = smem_u32(smem);

    int tid  = threadIdx.x;
    int lane = tid & 31, wid = tid >> 5;
    int wm = wid >> 2, wn = wid & 3;

    TilePtrs tp;
    {
        int r0 = tid >> 3, sg = tid & 7;
#pragma unroll
        for (int i = 0; i < 4; i++) {
            int r = r0 + 32 * i;
            tp.a[i]  = g_h + (size_t)(base + rb + r) * DH + sg * 8;  // HPAD covers tails
            tp.asz[i] = 16;
        }
        tp.aDst = (uint32_t)r0 * 144 + sg * 16;
        tp.aStep = BK;
        int kr0 = tid >> 4, bs = tid & 15;
        size_t wbase = (size_t)e * DH * DM;
        tp.b = g_w2 + wbase + (size_t)kr0 * DM + nb + bs * 8;
        tp.bDst = (uint32_t)kr0 * 272 + bs * 16;
        tp.bStep = BK * DM;
        tp.bRowStride = 16 * DM;
    }

    uint32_t aOff = calc_aoff(wm, lane);
    uint32_t bOff = calc_boff(wn, lane);

    float cacc[4][4][4];
#pragma unroll
    for (int mi = 0; mi < 4; mi++)
#pragma unroll
        for (int ni = 0; ni < 4; ni++)
#pragma unroll
            for (int q = 0; q < 4; q++) cacc[mi][ni][q] = 0.0f;

    gemm_core<DH / BK>(sb, tp, cacc, aOff, bOff);

    const float* bb = b2 + (size_t)e * DM + nb;
    int er = wm * 64 + (lane >> 2);
    int ec = wn * 32 + (lane & 3) * 2;
#pragma unroll
    for (int mi = 0; mi < 4; mi++) {
#pragma unroll
        for (int rr = 0; rr < 2; rr++) {
            int m = er + mi * 16 + rr * 8;
            if (rb + m >= cnt) continue;
            int   tok = g_tok[e * TT + rb + m];
            float w   = g_wt [e * TT + rb + m];
            float* orow = out + (size_t)tok * DM + nb;
#pragma unroll
            for (int ni = 0; ni < 4; ni++) {
                int c = ec + ni * 8;
                atomicAdd(&orow[c],     w * (cacc[mi][ni][rr * 2 + 0] + bb[c]));
                atomicAdd(&orow[c + 1], w * (cacc[mi][ni][rr * 2 + 1] + bb[c + 1]));
            }
        }
    }
}

// ===========================================================================
// Launch
// ===========================================================================
extern "C" void kernel_launch(void* const* d_in, const int* in_sizes, int n_in,
                              void* d_out, int out_size) {
    const float* x  = (const float*)d_in[0];
    const float* Wg = (const float*)d_in[1];
    const float* bg = (const float*)d_in[2];
    const float* W1 = (const float*)d_in[3];
    const float* b1 = (const float*)d_in[4];
    const float* W2 = (const float*)d_in[5];
    const float* b2 = (const float*)d_in[6];

    float* out_y = (float*)d_out;
    int write_logits = (out_size >= TT * (DM + NE)) ? 1 : 0;
    float* logits = out_y + (size_t)TT * DM;

    cudaFuncSetAttribute(moe_gemm1, cudaFuncAttributeMaxDynamicSharedMemorySize, SMEM_BYTES);
    cudaFuncSetAttribute(moe_gemm2, cudaFuncAttributeMaxDynamicSharedMemorySize, SMEM_BYTES);

    __half *w1p, *w2p;
    cudaGetSymbolAddress((void**)&w1p, g_w1);
    cudaGetSymbolAddress((void**)&w2p, g_w2);
    int* cntp;
    cudaGetSymbolAddress((void**)&cntp, g_cnt);

    cudaMemsetAsync(cntp, 0, NE * sizeof(int));
    cudaMemsetAsync(out_y, 0, (size_t)TT * DM * sizeof(float));

    prep_kernel<<<GATE_BLKS + CONV_BLKS, 256>>>(x, Wg, bg, W1, w1p,
                                                logits, write_logits);

    moe_gemm1<<<dim3(DH / BN, TT / BM, NE), NTHREADS, SMEM_BYTES>>>(b1, W2, w2p);
    moe_gemm2<<<dim3(DM / BN, TT / BM, NE), NTHREADS, SMEM_BYTES>>>(b2, out_y);
}